// round 11
// baseline (speedup 1.0000x reference)
#include <cuda_runtime.h>
#include <cuda_fp16.h>
#include <cstdint>
#include <math.h>

#define HW     3600
#define NB     2
#define CK     3072      // 2048 + 1024 stacked channels
#define C4     2048
#define C3     1024
#define CQ     256
#define KP     3648      // HW padded for attn GEMM K dim
#define TEMP   20.0f
#define ATT_WT 0.5f
#define EPS    1e-12f

#define SZ3    (NB * C3 * HW)
#define SZ4    (NB * C4 * HW)
#define SZQ    (NB * CQ * HW)

// ---------------- scratch ----------------------------------------------------
__device__ __half g_Ah[(size_t)NB * HW * CK];     // norm q feats half K-major [b][m][k]
__device__ __half g_Bh[(size_t)NB * HW * CK];     // norm s feats half K-major [b][n][k]
__device__ __half g_attnH[(size_t)NB * HW * KP];  // softmaxed attn half      [b][q][s pad]
__device__ __half g_Vh[(size_t)NB * CQ * KP];     // f_s half                 [b][c][s pad]
__device__ float  g_corr[(size_t)NB * HW * HW];   // corr logits (x10)        [b][q][s]
__device__ float  g_attP[(size_t)NB * 2 * CQ * HW]; // split-K partials       [b*2+k][c][q]
__device__ float  g_nrm[16 * NB * HW];            // partial sumsq [sel4][quarter4][b][p]

__device__ __forceinline__ uint32_t smem_u32(const void* p) {
    uint32_t a;
    asm("{ .reg .u64 t; cvta.to.shared.u64 t, %1; cvt.u32.u64 %0, t; }" : "=r"(a) : "l"(p));
    return a;
}
__device__ __forceinline__ void mma_f16(float* d, const uint32_t* a, const uint32_t* b) {
    asm volatile(
        "mma.sync.aligned.m16n8k16.row.col.f32.f16.f16.f32 "
        "{%0,%1,%2,%3}, {%4,%5,%6,%7}, {%8,%9}, {%0,%1,%2,%3};"
        : "+f"(d[0]), "+f"(d[1]), "+f"(d[2]), "+f"(d[3])
        : "r"(a[0]), "r"(a[1]), "r"(a[2]), "r"(a[3]), "r"(b[0]), "r"(b[1]));
}

// ---------------- 1a) partial sum-of-squares, float4 along pixels -------------
__global__ void norms4_kernel(const float* __restrict__ inA,
                              const float* __restrict__ inB,
                              int Cf, int selbase) {
    int which = blockIdx.y;               // 0 = q tensor, 1 = s tensor
    const float* in = which ? inB : inA;
    int sel = selbase + which;
    int b   = blockIdx.x / 57;
    int p0  = (blockIdx.x % 57) * 64;
    int cq  = blockIdx.z;                 // channel quarter 0..3
    int Cq  = Cf >> 2;
    int tid = threadIdx.x;
    int px4 = tid & 15;                   // float4 column within 64 px
    int cg  = tid >> 4;                   // 0..15
    bool pv = (p0 + 4 * px4 + 3 < HW);

    float4 a = make_float4(0.f, 0.f, 0.f, 0.f);
    if (pv) {
        const float* base = in + ((size_t)b * Cf + (size_t)cq * Cq) * HW + p0 + 4 * px4;
        #pragma unroll 4
        for (int c = cg; c < Cq; c += 16) {
            float4 x = *(const float4*)(base + (size_t)c * HW);
            a.x += x.x * x.x; a.y += x.y * x.y; a.z += x.z * x.z; a.w += x.w * x.w;
        }
    }
    __shared__ float part[16][64];
    part[cg][4 * px4 + 0] = a.x;
    part[cg][4 * px4 + 1] = a.y;
    part[cg][4 * px4 + 2] = a.z;
    part[cg][4 * px4 + 3] = a.w;
    __syncthreads();
    if (tid < 64 && p0 + tid < HW) {
        float t = 0.f;
        #pragma unroll
        for (int g = 0; g < 16; g++) t += part[g][tid];
        g_nrm[(((size_t)sel * 4 + cq) * NB + b) * HW + p0 + tid] = t;
    }
}

// ---------------- 1b) scale + transpose + half into K-major ------------------
__global__ void transpose_kernel(const float* __restrict__ in, int Cf, int coff,
                                 int sel /*0=A 1=B*/, int nsel) {
    __shared__ __half sh[32][66];
    int b  = blockIdx.z;
    int c0 = blockIdx.y * 64;
    int p0 = blockIdx.x * 32;
    int tid = threadIdx.x;
    int tx = tid & 31, ty = tid >> 5;       // ty 0..7

    int p = p0 + tx;
    bool pv = (p < HW);
    float inv = 0.f;
    if (pv) {
        size_t nb = ((size_t)nsel * 4 * NB + b) * HW + p;
        float s = g_nrm[nb] + g_nrm[nb + (size_t)NB * HW]
                + g_nrm[nb + (size_t)2 * NB * HW] + g_nrm[nb + (size_t)3 * NB * HW];
        inv = 1.f / fmaxf(sqrtf(s), EPS);
    }
    const float* X = in + ((size_t)b * Cf + c0) * HW + p;
    #pragma unroll
    for (int j = 0; j < 8; j++) {
        int c = ty * 8 + j;
        float v = pv ? X[(size_t)c * HW] : 0.f;
        sh[tx][c] = __float2half_rn(v * inv);
    }
    __syncthreads();
    __half* T = (sel ? g_Bh : g_Ah) + (size_t)b * HW * CK + coff + c0;
    #pragma unroll
    for (int k = 0; k < 4; k++) {
        int e  = tid + k * 256;
        int pr = e >> 5;
        int ln = e & 31;
        if (p0 + pr < HW) {
            uint32_t w = *(const uint32_t*)&sh[pr][2 * ln];
            *(uint32_t*)&T[(size_t)(p0 + pr) * CK + 2 * ln] = w;
        }
    }
}

// ---------------- 2a) corr GEMM: 144x144 exact tiles, 9 warps (3x3, 48x48) ---
// C[m][n] = 10 * sum_k A[m][k]*B[n][k];  3600 = 25*144, no bounds anywhere.
#define T144      144
#define SROW144   72                       // halves per smem row (64 data + 8 pad)
#define ROWB144   144                      // bytes per smem row
#define STG144    (288 * ROWB144)          // 41472 B per stage
#define SMEM144   (2 * STG144)             // 82944 B

__global__ __launch_bounds__(288, 2)
void gemm_corr144() {
    extern __shared__ __align__(16) char smh[];
    uint32_t sbase = smem_u32(smh);
    int tid = threadIdx.x;
    int wid = tid >> 5, lane = tid & 31;
    int grp = lane >> 2, tig = lane & 3;
    int wm = (wid % 3) * 48;
    int wn = (wid / 3) * 48;
    int b  = blockIdx.z;
    int m0 = blockIdx.y * T144;
    int n0 = blockIdx.x * T144;
    const __half* A = g_Ah + (size_t)b * HW * CK;
    const __half* B = g_Bh + (size_t)b * HW * CK;
    float* Cb = g_corr + (size_t)b * HW * HW;

    float acc[3][6][4];
    #pragma unroll
    for (int mi = 0; mi < 3; mi++)
        #pragma unroll
        for (int ni = 0; ni < 6; ni++)
            #pragma unroll
            for (int j = 0; j < 4; j++) acc[mi][ni][j] = 0.f;

    auto load_tile = [&](int iter, int s) {
        int k0 = iter * 64;                   // halves
        uint32_t st = sbase + s * STG144;
        #pragma unroll
        for (int j = 0; j < 8; j++) {         // 2304 chunks / 288 threads
            int f = tid + j * 288;
            int row = f >> 3, q = f & 7;
            const __half* gp = (row < T144)
                ? A + (size_t)(m0 + row) * CK + k0 + q * 8
                : B + (size_t)(n0 + row - T144) * CK + k0 + q * 8;
            uint32_t sa = st + row * ROWB144 + q * 16;
            asm volatile("cp.async.cg.shared.global [%0], [%1], 16;"
                         :: "r"(sa), "l"(gp) : "memory");
        }
        asm volatile("cp.async.commit_group;" ::: "memory");
    };

    const int NIT = CK / 64;   // 48
    load_tile(0, 0);
    load_tile(1, 1);

    for (int i = 0; i < NIT; i++) {
        int s = i & 1;
        if (i + 1 < NIT) { asm volatile("cp.async.wait_group 1;" ::: "memory"); }
        else            { asm volatile("cp.async.wait_group 0;" ::: "memory"); }
        __syncthreads();

        const __half* as = (const __half*)(smh + (size_t)s * STG144);
        const __half* bs = as + T144 * SROW144;
        #pragma unroll
        for (int ks = 0; ks < 4; ks++) {
            int kk = ks * 16;
            uint32_t af[3][4];
            #pragma unroll
            for (int mi = 0; mi < 3; mi++) {
                int r = wm + mi * 16 + grp;
                af[mi][0] = *(const uint32_t*)&as[r * SROW144 + kk + 2 * tig];
                af[mi][1] = *(const uint32_t*)&as[(r + 8) * SROW144 + kk + 2 * tig];
                af[mi][2] = *(const uint32_t*)&as[r * SROW144 + kk + 8 + 2 * tig];
                af[mi][3] = *(const uint32_t*)&as[(r + 8) * SROW144 + kk + 8 + 2 * tig];
            }
            #pragma unroll
            for (int ni = 0; ni < 6; ni++) {
                int r = wn + ni * 8 + grp;
                uint32_t bf[2];
                bf[0] = *(const uint32_t*)&bs[r * SROW144 + kk + 2 * tig];
                bf[1] = *(const uint32_t*)&bs[r * SROW144 + kk + 8 + 2 * tig];
                #pragma unroll
                for (int mi = 0; mi < 3; mi++)
                    mma_f16(acc[mi][ni], af[mi], bf);
            }
        }
        __syncthreads();
        if (i + 2 < NIT) load_tile(i + 2, s);
    }

    #pragma unroll
    for (int mi = 0; mi < 3; mi++) {
        int mrow = m0 + wm + mi * 16 + grp;
        #pragma unroll
        for (int ni = 0; ni < 6; ni++) {
            int n = n0 + wn + ni * 8 + 2 * tig;
            *(float2*)&Cb[(size_t)mrow * HW + n] =
                make_float2(10.f * acc[mi][ni][0], 10.f * acc[mi][ni][1]);
            *(float2*)&Cb[(size_t)(mrow + 8) * HW + n] =
                make_float2(10.f * acc[mi][ni][2], 10.f * acc[mi][ni][3]);
        }
    }
}

// ---------------- 2b) attn GEMM: 128x128, split-K (unchanged from R10) -------
#define SROW_H  72
#define ROW_B   144
#define STG_B   (256 * ROW_B)
#define GEMM_SMEM (2 * STG_B)

__global__ __launch_bounds__(256, 2)
void gemm_h(const __half* __restrict__ Aall, const __half* __restrict__ Ball,
            float* __restrict__ Call, int ldk, int nIter, int Mg, int Ng,
            size_t strideA, size_t strideB, size_t strideC, float cs, int nSplit) {
    extern __shared__ __align__(16) char smh[];
    uint32_t sbase = smem_u32(smh);
    int tid = threadIdx.x;
    int wid = tid >> 5, lane = tid & 31;
    int grp = lane >> 2, tig = lane & 3;
    int wm = (wid & 3) * 32;
    int wn = (wid >> 2) * 64;
    int z   = blockIdx.z;
    int b   = z / nSplit;
    int ksp = z - b * nSplit;
    int m0 = blockIdx.y * 128;
    int n0 = blockIdx.x * 128;
    const __half* A = Aall + (size_t)b * strideA;
    const __half* B = Ball + (size_t)b * strideB;
    float* Cb = Call + (size_t)z * strideC;

    int per = (nIter + nSplit - 1) / nSplit;
    int i0  = ksp * per;
    int i1  = min(nIter, i0 + per);

    float acc[2][8][4];
    #pragma unroll
    for (int mi = 0; mi < 2; mi++)
        #pragma unroll
        for (int ni = 0; ni < 8; ni++)
            #pragma unroll
            for (int j = 0; j < 4; j++) acc[mi][ni][j] = 0.f;

    auto load_tile = [&](int iter, int s) {
        int k0 = iter * 64;
        uint32_t stA = sbase + s * STG_B;
        #pragma unroll
        for (int j = 0; j < 4; j++) {
            int f = tid + j * 256;
            int row = f >> 3, q = f & 7;
            uint32_t nb = (m0 + row < Mg) ? 16u : 0u;
            const __half* gp = A + (size_t)(nb ? m0 + row : 0) * ldk + k0 + q * 8;
            uint32_t sa = stA + row * ROW_B + q * 16;
            asm volatile("cp.async.cg.shared.global [%0], [%1], 16, %2;"
                         :: "r"(sa), "l"(gp), "r"(nb) : "memory");
        }
        #pragma unroll
        for (int j = 0; j < 4; j++) {
            int f = tid + j * 256;
            int row = f >> 3, q = f & 7;
            uint32_t nb = (n0 + row < Ng) ? 16u : 0u;
            const __half* gp = B + (size_t)(nb ? n0 + row : 0) * ldk + k0 + q * 8;
            uint32_t sa = stA + 128 * ROW_B + row * ROW_B + q * 16;
            asm volatile("cp.async.cg.shared.global [%0], [%1], 16, %2;"
                         :: "r"(sa), "l"(gp), "r"(nb) : "memory");
        }
        asm volatile("cp.async.commit_group;" ::: "memory");
    };

    load_tile(i0, 0);
    if (i0 + 1 < i1) load_tile(i0 + 1, 1);

    for (int i = i0; i < i1; i++) {
        int s = (i - i0) & 1;
        if (i + 1 < i1) { asm volatile("cp.async.wait_group 1;" ::: "memory"); }
        else           { asm volatile("cp.async.wait_group 0;" ::: "memory"); }
        __syncthreads();

        const __half* as = (const __half*)(smh + (size_t)s * STG_B);
        const __half* bs = as + 128 * SROW_H;
        #pragma unroll
        for (int ks = 0; ks < 4; ks++) {
            int kk = ks * 16;
            uint32_t af[2][4];
            #pragma unroll
            for (int mi = 0; mi < 2; mi++) {
                int r = wm + mi * 16 + grp;
                af[mi][0] = *(const uint32_t*)&as[r * SROW_H + kk + 2 * tig];
                af[mi][1] = *(const uint32_t*)&as[(r + 8) * SROW_H + kk + 2 * tig];
                af[mi][2] = *(const uint32_t*)&as[r * SROW_H + kk + 8 + 2 * tig];
                af[mi][3] = *(const uint32_t*)&as[(r + 8) * SROW_H + kk + 8 + 2 * tig];
            }
            #pragma unroll
            for (int ni = 0; ni < 8; ni++) {
                int r = wn + ni * 8 + grp;
                uint32_t bf[2];
                bf[0] = *(const uint32_t*)&bs[r * SROW_H + kk + 2 * tig];
                bf[1] = *(const uint32_t*)&bs[r * SROW_H + kk + 8 + 2 * tig];
                #pragma unroll
                for (int mi = 0; mi < 2; mi++)
                    mma_f16(acc[mi][ni], af[mi], bf);
            }
        }
        __syncthreads();
        if (i + 2 < i1) load_tile(i + 2, s);
    }

    #pragma unroll
    for (int mi = 0; mi < 2; mi++) {
        int mrow = m0 + wm + mi * 16 + grp;
        #pragma unroll
        for (int ni = 0; ni < 8; ni++) {
            int n = n0 + wn + ni * 8 + 2 * tig;
            if (n < Ng) {
                if (mrow < Mg)
                    *(float2*)&Cb[(size_t)mrow * HW + n] =
                        make_float2(cs * acc[mi][ni][0], cs * acc[mi][ni][1]);
                if (mrow + 8 < Mg)
                    *(float2*)&Cb[(size_t)(mrow + 8) * HW + n] =
                        make_float2(cs * acc[mi][ni][2], cs * acc[mi][ni][3]);
            }
        }
    }
}

// ---------------- 3) row softmax (logits pre-scaled x10), vectorized ---------
__device__ __forceinline__ float warpRedMax(float v) {
    #pragma unroll
    for (int o = 16; o; o >>= 1) v = fmaxf(v, __shfl_xor_sync(0xffffffffu, v, o));
    return v;
}
__device__ __forceinline__ float warpRedSum(float v) {
    #pragma unroll
    for (int o = 16; o; o >>= 1) v += __shfl_xor_sync(0xffffffffu, v, o);
    return v;
}

__global__ void softmax_kernel() {
    int row = blockIdx.x;                          // 0 .. NB*HW-1
    const float4* base = (const float4*)(g_corr + (size_t)row * HW);
    __half* outp = g_attnH + (size_t)row * KP;
    int tid = threadIdx.x;
    __shared__ float red[8];

    float4 v[4];
    float mx = -1e30f;
    #pragma unroll
    for (int i = 0; i < 4; i++) {
        int i4 = tid + i * 256;                    // float4 index, 900 valid
        if (i4 < HW / 4) {
            v[i] = base[i4];
            mx = fmaxf(mx, fmaxf(fmaxf(v[i].x, v[i].y), fmaxf(v[i].z, v[i].w)));
        } else {
            v[i] = make_float4(-1e30f, -1e30f, -1e30f, -1e30f);
        }
    }
    mx = warpRedMax(mx);
    if ((tid & 31) == 0) red[tid >> 5] = mx;
    __syncthreads();
    if (tid < 32) {
        float t = (tid < 8) ? red[tid] : -1e30f;
        t = warpRedMax(t);
        if (tid == 0) red[0] = t;
    }
    __syncthreads();
    mx = red[0];
    __syncthreads();

    float sum = 0.f;
    #pragma unroll
    for (int i = 0; i < 4; i++) {
        int i4 = tid + i * 256;
        if (i4 < HW / 4) {
            v[i].x = expf(v[i].x - mx); v[i].y = expf(v[i].y - mx);
            v[i].z = expf(v[i].z - mx); v[i].w = expf(v[i].w - mx);
            sum += v[i].x + v[i].y + v[i].z + v[i].w;
        }
    }
    sum = warpRedSum(sum);
    if ((tid & 31) == 0) red[tid >> 5] = sum;
    __syncthreads();
    if (tid < 32) {
        float t = (tid < 8) ? red[tid] : 0.f;
        t = warpRedSum(t);
        if (tid == 0) red[0] = t;
    }
    __syncthreads();
    float r = 1.f / red[0];

    #pragma unroll
    for (int i = 0; i < 4; i++) {
        int i4 = tid + i * 256;
        if (i4 < HW / 4) {
            __half2 h01 = __floats2half2_rn(v[i].x * r, v[i].y * r);
            __half2 h23 = __floats2half2_rn(v[i].z * r, v[i].w * r);
            uint2 w = make_uint2(*(uint32_t*)&h01, *(uint32_t*)&h23);
            *(uint2*)&outp[4 * i4] = w;
        }
    }
    if (tid < (KP - HW) / 4)
        *(uint2*)&outp[HW + 4 * tid] = make_uint2(0u, 0u);
}

// ---------------- 4) f_s -> half, K-padded ------------------------------------
__global__ void vprep_kernel(const float* __restrict__ V) {
    int idx = blockIdx.x * blockDim.x + threadIdx.x;
    if (idx >= NB * CQ * KP) return;
    int s = idx % KP;
    int bc = idx / KP;
    g_Vh[idx] = __float2half_rn(s < HW ? V[(size_t)bc * HW + s] : 0.f);
}

// ---------------- 5) combine (+ fused split-K reduce, + att output) ----------
__global__ void combine_kernel(const float* __restrict__ f_q,
                               float* __restrict__ out_fq,
                               float* __restrict__ out_att, int writeAtt) {
    int idx = blockIdx.x * blockDim.x + threadIdx.x;
    if (idx >= NB * HW) return;
    int b = idx / HW, p = idx % HW;
    const float* qb = f_q + (size_t)b * CQ * HW + p;
    const float* a0 = g_attP + ((size_t)2 * b) * CQ * HW + p;
    const float* a1 = g_attP + ((size_t)2 * b + 1) * CQ * HW + p;
    float sq = 0.f, sa = 0.f;
    #pragma unroll 8
    for (int c = 0; c < CQ; c++) {
        float x = qb[(size_t)c * HW]; sq += x * x;
        float y = a0[(size_t)c * HW] + a1[(size_t)c * HW]; sa += y * y;
    }
    float iq = 1.f / fmaxf(sqrtf(sq), EPS);
    float ia = ATT_WT / fmaxf(sqrtf(sa), EPS);
    float* ob = out_fq + (size_t)b * CQ * HW + p;
    if (writeAtt) {
        float* oa = out_att + (size_t)b * CQ * HW + p;
        #pragma unroll 4
        for (int c = 0; c < CQ; c++) {
            float y = a0[(size_t)c * HW] + a1[(size_t)c * HW];
            ob[(size_t)c * HW] = qb[(size_t)c * HW] * iq + y * ia;
            oa[(size_t)c * HW] = y;
        }
    } else {
        #pragma unroll 4
        for (int c = 0; c < CQ; c++) {
            float y = a0[(size_t)c * HW] + a1[(size_t)c * HW];
            ob[(size_t)c * HW] = qb[(size_t)c * HW] * iq + y * ia;
        }
    }
}

// ---------------- launch ------------------------------------------------------
extern "C" void kernel_launch(void* const* d_in, const int* in_sizes, int n_in,
                              void* d_out, int out_size) {
    const float *fq3 = 0, *fs3 = 0, *fq4 = 0, *fs4 = 0, *f_q = 0, *f_s = 0;
    for (int i = 0; i < n_in; i++) {
        const float* p = (const float*)d_in[i];
        int sz = in_sizes[i];
        if (sz == SZ3)      { if (!fq3) fq3 = p; else fs3 = p; }
        else if (sz == SZ4) { if (!fq4) fq4 = p; else fs4 = p; }
        else if (sz == SZQ) { if (!f_q) f_q = p; else f_s = p; }
    }
    float* out = (float*)d_out;

    // TRUE device addresses (host shadow symbols are ATS-dereferenceable on
    // GB300 -> silent zero-data bug if passed directly).
    void *pAttnH, *pVh, *pAttP;
    cudaGetSymbolAddress(&pAttnH, g_attnH);
    cudaGetSymbolAddress(&pVh, g_Vh);
    cudaGetSymbolAddress(&pAttP, g_attP);

    cudaFuncSetAttribute(gemm_corr144, cudaFuncAttributeMaxDynamicSharedMemorySize, SMEM144);
    cudaFuncSetAttribute(gemm_h, cudaFuncAttributeMaxDynamicSharedMemorySize, GEMM_SMEM);

    norms4_kernel<<<dim3(114, 2, 4), 256>>>(fq4, fs4, C4, 0);
    norms4_kernel<<<dim3(114, 2, 4), 256>>>(fq3, fs3, C3, 2);

    transpose_kernel<<<dim3(113, C4 / 64, NB), 256>>>(fq4, C4, 0,  0, 0);
    transpose_kernel<<<dim3(113, C4 / 64, NB), 256>>>(fs4, C4, 0,  1, 1);
    transpose_kernel<<<dim3(113, C3 / 64, NB), 256>>>(fq3, C3, C4, 0, 2);
    transpose_kernel<<<dim3(113, C3 / 64, NB), 256>>>(fs3, C3, C4, 1, 3);

    vprep_kernel<<<(NB * CQ * KP + 255) / 256, 256>>>(f_s);

    // corr logits (x10 = 0.5 mean * 20 temp folded into epilogue), exact tiles
    gemm_corr144<<<dim3(HW / T144, HW / T144, NB), 288, SMEM144>>>();

    softmax_kernel<<<NB * HW, 256>>>();

    // attn GEMM with split-K=2: partials into g_attP (reduced inside combine)
    gemm_h<<<dim3(29, 2, NB * 2), 256, GEMM_SMEM>>>(
        (const __half*)pVh, (const __half*)pAttnH, (float*)pAttP,
        KP, KP / 64, CQ, HW,
        (size_t)CQ * KP, (size_t)HW * KP, (size_t)CQ * HW, 1.0f, 2);

    int writeAtt = (out_size >= 2 * SZQ) ? 1 : 0;
    combine_kernel<<<29, 256>>>(f_q, out, out + SZQ, writeAtt);
}

// round 12
// speedup vs baseline: 1.0991x; 1.0991x over previous
#include <cuda_runtime.h>
#include <cuda_fp16.h>
#include <cstdint>
#include <math.h>

#define HW     3600
#define NB     2
#define CK     3072      // 2048 + 1024 stacked channels
#define C4     2048
#define C3     1024
#define CQ     256
#define KP     3648      // HW padded for attn GEMM K dim
#define TEMP   20.0f
#define ATT_WT 0.5f
#define EPS    1e-12f

#define SZ3    (NB * C3 * HW)
#define SZ4    (NB * C4 * HW)
#define SZQ    (NB * CQ * HW)

// ---------------- scratch ----------------------------------------------------
__device__ __half g_Ah[(size_t)NB * HW * CK];     // norm q feats half K-major [b][m][k]
__device__ __half g_Bh[(size_t)NB * HW * CK];     // norm s feats half K-major [b][n][k]
__device__ __half g_attnH[(size_t)NB * HW * KP];  // softmaxed attn half      [b][q][s pad]
__device__ __half g_Vh[(size_t)NB * CQ * KP];     // f_s half                 [b][c][s pad]
__device__ float  g_corr[(size_t)NB * HW * HW];   // corr logits (x10)        [b][q][s]
__device__ float  g_attP[(size_t)NB * 2 * CQ * HW]; // split-K partials       [b*2+k][c][q]
__device__ float  g_nrm[16 * NB * HW];            // partial sumsq [sel4][quarter4][b][p]

__device__ __forceinline__ uint32_t smem_u32(const void* p) {
    uint32_t a;
    asm("{ .reg .u64 t; cvta.to.shared.u64 t, %1; cvt.u32.u64 %0, t; }" : "=r"(a) : "l"(p));
    return a;
}
__device__ __forceinline__ void mma_f16(float* d, const uint32_t* a, const uint32_t* b) {
    asm volatile(
        "mma.sync.aligned.m16n8k16.row.col.f32.f16.f16.f32 "
        "{%0,%1,%2,%3}, {%4,%5,%6,%7}, {%8,%9}, {%0,%1,%2,%3};"
        : "+f"(d[0]), "+f"(d[1]), "+f"(d[2]), "+f"(d[3])
        : "r"(a[0]), "r"(a[1]), "r"(a[2]), "r"(a[3]), "r"(b[0]), "r"(b[1]));
}

// ---------------- 1a) partial sum-of-squares, float4 along pixels -------------
__global__ void norms4_kernel(const float* __restrict__ inA,
                              const float* __restrict__ inB,
                              int Cf, int selbase) {
    int which = blockIdx.y;               // 0 = q tensor, 1 = s tensor
    const float* in = which ? inB : inA;
    int sel = selbase + which;
    int b   = blockIdx.x / 57;
    int p0  = (blockIdx.x % 57) * 64;
    int cq  = blockIdx.z;                 // channel quarter 0..3
    int Cq  = Cf >> 2;
    int tid = threadIdx.x;
    int px4 = tid & 15;                   // float4 column within 64 px
    int cg  = tid >> 4;                   // 0..15
    bool pv = (p0 + 4 * px4 + 3 < HW);

    float4 a = make_float4(0.f, 0.f, 0.f, 0.f);
    if (pv) {
        const float* base = in + ((size_t)b * Cf + (size_t)cq * Cq) * HW + p0 + 4 * px4;
        #pragma unroll 4
        for (int c = cg; c < Cq; c += 16) {
            float4 x = *(const float4*)(base + (size_t)c * HW);
            a.x += x.x * x.x; a.y += x.y * x.y; a.z += x.z * x.z; a.w += x.w * x.w;
        }
    }
    __shared__ float part[16][64];
    part[cg][4 * px4 + 0] = a.x;
    part[cg][4 * px4 + 1] = a.y;
    part[cg][4 * px4 + 2] = a.z;
    part[cg][4 * px4 + 3] = a.w;
    __syncthreads();
    if (tid < 64 && p0 + tid < HW) {
        float t = 0.f;
        #pragma unroll
        for (int g = 0; g < 16; g++) t += part[g][tid];
        g_nrm[(((size_t)sel * 4 + cq) * NB + b) * HW + p0 + tid] = t;
    }
}

// ---------------- 1b) scale + transpose + half into K-major ------------------
__global__ void transpose_kernel(const float* __restrict__ in, int Cf, int coff,
                                 int sel /*0=A 1=B*/, int nsel) {
    __shared__ __half sh[32][66];
    int b  = blockIdx.z;
    int c0 = blockIdx.y * 64;
    int p0 = blockIdx.x * 32;
    int tid = threadIdx.x;
    int tx = tid & 31, ty = tid >> 5;       // ty 0..7

    int p = p0 + tx;
    bool pv = (p < HW);
    float inv = 0.f;
    if (pv) {
        size_t nb = ((size_t)nsel * 4 * NB + b) * HW + p;
        float s = g_nrm[nb] + g_nrm[nb + (size_t)NB * HW]
                + g_nrm[nb + (size_t)2 * NB * HW] + g_nrm[nb + (size_t)3 * NB * HW];
        inv = 1.f / fmaxf(sqrtf(s), EPS);
    }
    const float* X = in + ((size_t)b * Cf + c0) * HW + p;
    #pragma unroll
    for (int j = 0; j < 8; j++) {
        int c = ty * 8 + j;
        float v = pv ? X[(size_t)c * HW] : 0.f;
        sh[tx][c] = __float2half_rn(v * inv);
    }
    __syncthreads();
    __half* T = (sel ? g_Bh : g_Ah) + (size_t)b * HW * CK + coff + c0;
    #pragma unroll
    for (int k = 0; k < 4; k++) {
        int e  = tid + k * 256;
        int pr = e >> 5;
        int ln = e & 31;
        if (p0 + pr < HW) {
            uint32_t w = *(const uint32_t*)&sh[pr][2 * ln];
            *(uint32_t*)&T[(size_t)(p0 + pr) * CK + 2 * ln] = w;
        }
    }
}

// ---------------- 2) generic fp16 GEMM (optional split-K) --------------------
// C[z][m][n] = cs * sum_{k in split} A[m][k]*B[n][k];  z = b*nSplit + ksp
#define SROW_H  72
#define ROW_B   144
#define STG_B   (256 * ROW_B)              // 36864 B
#define GEMM_SMEM (2 * STG_B)              // 73728 B -> 2 CTAs/SM

__global__ __launch_bounds__(256, 2)
void gemm_h(const __half* __restrict__ Aall, const __half* __restrict__ Ball,
            float* __restrict__ Call, int ldk, int nIter, int Mg, int Ng,
            size_t strideA, size_t strideB, size_t strideC, float cs, int nSplit) {
    extern __shared__ __align__(16) char smh[];
    uint32_t sbase = smem_u32(smh);
    int tid = threadIdx.x;
    int wid = tid >> 5, lane = tid & 31;
    int grp = lane >> 2, tig = lane & 3;
    int wm = (wid & 3) * 32;
    int wn = (wid >> 2) * 64;
    int z   = blockIdx.z;
    int b   = z / nSplit;
    int ksp = z - b * nSplit;
    int m0 = blockIdx.y * 128;
    int n0 = blockIdx.x * 128;
    const __half* A = Aall + (size_t)b * strideA;
    const __half* B = Ball + (size_t)b * strideB;
    float* Cb = Call + (size_t)z * strideC;

    int per = (nIter + nSplit - 1) / nSplit;
    int i0  = ksp * per;
    int i1  = min(nIter, i0 + per);

    float acc[2][8][4];
    #pragma unroll
    for (int mi = 0; mi < 2; mi++)
        #pragma unroll
        for (int ni = 0; ni < 8; ni++)
            #pragma unroll
            for (int j = 0; j < 4; j++) acc[mi][ni][j] = 0.f;

    auto load_tile = [&](int iter, int s) {
        int k0 = iter * 64;                   // halves
        uint32_t stA = sbase + s * STG_B;
        #pragma unroll
        for (int j = 0; j < 4; j++) {         // A: 128 rows x 8 chunks
            int f = tid + j * 256;
            int row = f >> 3, q = f & 7;
            uint32_t nb = (m0 + row < Mg) ? 16u : 0u;
            const __half* gp = A + (size_t)(nb ? m0 + row : 0) * ldk + k0 + q * 8;
            uint32_t sa = stA + row * ROW_B + q * 16;
            asm volatile("cp.async.cg.shared.global [%0], [%1], 16, %2;"
                         :: "r"(sa), "l"(gp), "r"(nb) : "memory");
        }
        #pragma unroll
        for (int j = 0; j < 4; j++) {         // B: 128 rows x 8 chunks
            int f = tid + j * 256;
            int row = f >> 3, q = f & 7;
            uint32_t nb = (n0 + row < Ng) ? 16u : 0u;
            const __half* gp = B + (size_t)(nb ? n0 + row : 0) * ldk + k0 + q * 8;
            uint32_t sa = stA + 128 * ROW_B + row * ROW_B + q * 16;
            asm volatile("cp.async.cg.shared.global [%0], [%1], 16, %2;"
                         :: "r"(sa), "l"(gp), "r"(nb) : "memory");
        }
        asm volatile("cp.async.commit_group;" ::: "memory");
    };

    load_tile(i0, 0);
    if (i0 + 1 < i1) load_tile(i0 + 1, 1);

    for (int i = i0; i < i1; i++) {
        int s = (i - i0) & 1;
        if (i + 1 < i1) { asm volatile("cp.async.wait_group 1;" ::: "memory"); }
        else           { asm volatile("cp.async.wait_group 0;" ::: "memory"); }
        __syncthreads();

        const __half* as = (const __half*)(smh + (size_t)s * STG_B);
        const __half* bs = as + 128 * SROW_H;
        #pragma unroll
        for (int ks = 0; ks < 4; ks++) {
            int kk = ks * 16;
            uint32_t af[2][4];
            #pragma unroll
            for (int mi = 0; mi < 2; mi++) {
                int r = wm + mi * 16 + grp;
                af[mi][0] = *(const uint32_t*)&as[r * SROW_H + kk + 2 * tig];
                af[mi][1] = *(const uint32_t*)&as[(r + 8) * SROW_H + kk + 2 * tig];
                af[mi][2] = *(const uint32_t*)&as[r * SROW_H + kk + 8 + 2 * tig];
                af[mi][3] = *(const uint32_t*)&as[(r + 8) * SROW_H + kk + 8 + 2 * tig];
            }
            uint32_t bf[8][2];
            #pragma unroll
            for (int ni = 0; ni < 8; ni++) {
                int r = wn + ni * 8 + grp;
                bf[ni][0] = *(const uint32_t*)&bs[r * SROW_H + kk + 2 * tig];
                bf[ni][1] = *(const uint32_t*)&bs[r * SROW_H + kk + 8 + 2 * tig];
            }
            #pragma unroll
            for (int mi = 0; mi < 2; mi++)
                #pragma unroll
                for (int ni = 0; ni < 8; ni++)
                    mma_f16(acc[mi][ni], af[mi], bf[ni]);
        }
        __syncthreads();
        if (i + 2 < i1) load_tile(i + 2, s);
    }

    #pragma unroll
    for (int mi = 0; mi < 2; mi++) {
        int mrow = m0 + wm + mi * 16 + grp;
        #pragma unroll
        for (int ni = 0; ni < 8; ni++) {
            int n = n0 + wn + ni * 8 + 2 * tig;
            if (n < Ng) {
                if (mrow < Mg)
                    *(float2*)&Cb[(size_t)mrow * HW + n] =
                        make_float2(cs * acc[mi][ni][0], cs * acc[mi][ni][1]);
                if (mrow + 8 < Mg)
                    *(float2*)&Cb[(size_t)(mrow + 8) * HW + n] =
                        make_float2(cs * acc[mi][ni][2], cs * acc[mi][ni][3]);
            }
        }
    }
}

// ---------------- 3) row softmax (logits pre-scaled x10), vectorized ---------
__device__ __forceinline__ float warpRedMax(float v) {
    #pragma unroll
    for (int o = 16; o; o >>= 1) v = fmaxf(v, __shfl_xor_sync(0xffffffffu, v, o));
    return v;
}
__device__ __forceinline__ float warpRedSum(float v) {
    #pragma unroll
    for (int o = 16; o; o >>= 1) v += __shfl_xor_sync(0xffffffffu, v, o);
    return v;
}

__global__ void softmax_kernel() {
    int row = blockIdx.x;                          // 0 .. NB*HW-1
    const float4* base = (const float4*)(g_corr + (size_t)row * HW);
    __half* outp = g_attnH + (size_t)row * KP;
    int tid = threadIdx.x;
    __shared__ float red[8];

    float4 v[4];
    float mx = -1e30f;
    #pragma unroll
    for (int i = 0; i < 4; i++) {
        int i4 = tid + i * 256;                    // float4 index, 900 valid
        if (i4 < HW / 4) {
            v[i] = base[i4];
            mx = fmaxf(mx, fmaxf(fmaxf(v[i].x, v[i].y), fmaxf(v[i].z, v[i].w)));
        } else {
            v[i] = make_float4(-1e30f, -1e30f, -1e30f, -1e30f);
        }
    }
    mx = warpRedMax(mx);
    if ((tid & 31) == 0) red[tid >> 5] = mx;
    __syncthreads();
    if (tid < 32) {
        float t = (tid < 8) ? red[tid] : -1e30f;
        t = warpRedMax(t);
        if (tid == 0) red[0] = t;
    }
    __syncthreads();
    mx = red[0];
    __syncthreads();

    float sum = 0.f;
    #pragma unroll
    for (int i = 0; i < 4; i++) {
        int i4 = tid + i * 256;
        if (i4 < HW / 4) {
            v[i].x = expf(v[i].x - mx); v[i].y = expf(v[i].y - mx);
            v[i].z = expf(v[i].z - mx); v[i].w = expf(v[i].w - mx);
            sum += v[i].x + v[i].y + v[i].z + v[i].w;
        }
    }
    sum = warpRedSum(sum);
    if ((tid & 31) == 0) red[tid >> 5] = sum;
    __syncthreads();
    if (tid < 32) {
        float t = (tid < 8) ? red[tid] : 0.f;
        t = warpRedSum(t);
        if (tid == 0) red[0] = t;
    }
    __syncthreads();
    float r = 1.f / red[0];

    #pragma unroll
    for (int i = 0; i < 4; i++) {
        int i4 = tid + i * 256;
        if (i4 < HW / 4) {
            __half2 h01 = __floats2half2_rn(v[i].x * r, v[i].y * r);
            __half2 h23 = __floats2half2_rn(v[i].z * r, v[i].w * r);
            uint2 w = make_uint2(*(uint32_t*)&h01, *(uint32_t*)&h23);
            *(uint2*)&outp[4 * i4] = w;
        }
    }
    if (tid < (KP - HW) / 4)
        *(uint2*)&outp[HW + 4 * tid] = make_uint2(0u, 0u);
}

// ---------------- 4) f_s -> half, K-padded ------------------------------------
__global__ void vprep_kernel(const float* __restrict__ V) {
    int idx = blockIdx.x * blockDim.x + threadIdx.x;
    if (idx >= NB * CQ * KP) return;
    int s = idx % KP;
    int bc = idx / KP;
    g_Vh[idx] = __float2half_rn(s < HW ? V[(size_t)bc * HW + s] : 0.f);
}

// ---------------- 5) combine (+ fused split-K reduce, + att output) ----------
__global__ void combine_kernel(const float* __restrict__ f_q,
                               float* __restrict__ out_fq,
                               float* __restrict__ out_att, int writeAtt) {
    int idx = blockIdx.x * blockDim.x + threadIdx.x;
    if (idx >= NB * HW) return;
    int b = idx / HW, p = idx % HW;
    const float* qb = f_q + (size_t)b * CQ * HW + p;
    const float* a0 = g_attP + ((size_t)2 * b) * CQ * HW + p;
    const float* a1 = g_attP + ((size_t)2 * b + 1) * CQ * HW + p;
    float sq = 0.f, sa = 0.f;
    #pragma unroll 8
    for (int c = 0; c < CQ; c++) {
        float x = qb[(size_t)c * HW]; sq += x * x;
        float y = a0[(size_t)c * HW] + a1[(size_t)c * HW]; sa += y * y;
    }
    float iq = 1.f / fmaxf(sqrtf(sq), EPS);
    float ia = ATT_WT / fmaxf(sqrtf(sa), EPS);
    float* ob = out_fq + (size_t)b * CQ * HW + p;
    if (writeAtt) {
        float* oa = out_att + (size_t)b * CQ * HW + p;
        #pragma unroll 4
        for (int c = 0; c < CQ; c++) {
            float y = a0[(size_t)c * HW] + a1[(size_t)c * HW];
            ob[(size_t)c * HW] = qb[(size_t)c * HW] * iq + y * ia;
            oa[(size_t)c * HW] = y;
        }
    } else {
        #pragma unroll 4
        for (int c = 0; c < CQ; c++) {
            float y = a0[(size_t)c * HW] + a1[(size_t)c * HW];
            ob[(size_t)c * HW] = qb[(size_t)c * HW] * iq + y * ia;
        }
    }
}

// ---------------- launch ------------------------------------------------------
extern "C" void kernel_launch(void* const* d_in, const int* in_sizes, int n_in,
                              void* d_out, int out_size) {
    const float *fq3 = 0, *fs3 = 0, *fq4 = 0, *fs4 = 0, *f_q = 0, *f_s = 0;
    for (int i = 0; i < n_in; i++) {
        const float* p = (const float*)d_in[i];
        int sz = in_sizes[i];
        if (sz == SZ3)      { if (!fq3) fq3 = p; else fs3 = p; }
        else if (sz == SZ4) { if (!fq4) fq4 = p; else fs4 = p; }
        else if (sz == SZQ) { if (!f_q) f_q = p; else f_s = p; }
    }
    float* out = (float*)d_out;

    // TRUE device addresses (host shadow symbols are ATS-dereferenceable on
    // GB300 -> silent zero-data bug if passed directly).
    void *pAh, *pBh, *pAttnH, *pVh, *pCorr, *pAttP;
    cudaGetSymbolAddress(&pAh, g_Ah);
    cudaGetSymbolAddress(&pBh, g_Bh);
    cudaGetSymbolAddress(&pAttnH, g_attnH);
    cudaGetSymbolAddress(&pVh, g_Vh);
    cudaGetSymbolAddress(&pCorr, g_corr);
    cudaGetSymbolAddress(&pAttP, g_attP);

    cudaFuncSetAttribute(gemm_h, cudaFuncAttributeMaxDynamicSharedMemorySize, GEMM_SMEM);

    norms4_kernel<<<dim3(114, 2, 4), 256>>>(fq4, fs4, C4, 0);
    norms4_kernel<<<dim3(114, 2, 4), 256>>>(fq3, fs3, C3, 2);

    transpose_kernel<<<dim3(113, C4 / 64, NB), 256>>>(fq4, C4, 0,  0, 0);
    transpose_kernel<<<dim3(113, C4 / 64, NB), 256>>>(fs4, C4, 0,  1, 1);
    transpose_kernel<<<dim3(113, C3 / 64, NB), 256>>>(fq3, C3, C4, 0, 2);
    transpose_kernel<<<dim3(113, C3 / 64, NB), 256>>>(fs3, C3, C4, 1, 3);

    vprep_kernel<<<(NB * CQ * KP + 255) / 256, 256>>>(f_s);

    // corr logits (x10 = 0.5 mean * 20 temp folded into epilogue), R10 kernel
    gemm_h<<<dim3(29, 29, NB), 256, GEMM_SMEM>>>(
        (const __half*)pAh, (const __half*)pBh, (float*)pCorr,
        CK, CK / 64, HW, HW,
        (size_t)HW * CK, (size_t)HW * CK, (size_t)HW * HW, 10.0f, 1);

    softmax_kernel<<<NB * HW, 256>>>();

    // attn GEMM with split-K=2: partials into g_attP (reduced inside combine)
    gemm_h<<<dim3(29, 2, NB * 2), 256, GEMM_SMEM>>>(
        (const __half*)pVh, (const __half*)pAttnH, (float*)pAttP,
        KP, KP / 64, CQ, HW,
        (size_t)CQ * KP, (size_t)HW * KP, (size_t)CQ * HW, 1.0f, 2);

    int writeAtt = (out_size >= 2 * SZQ) ? 1 : 0;
    combine_kernel<<<29, 256>>>(f_q, out, out + SZQ, writeAtt);
}

// round 13
// speedup vs baseline: 1.1488x; 1.0452x over previous
#include <cuda_runtime.h>
#include <cuda_fp16.h>
#include <cstdint>
#include <math.h>

#define HW     3600
#define NB     2
#define CK     3072      // 2048 + 1024 stacked channels
#define C4     2048
#define C3     1024
#define CQ     256
#define KP     3648      // HW padded for attn GEMM K dim
#define NTB    29        // n-tile blocks in corr GEMM (29*128 >= 3600)
#define ATT_WT 0.5f
#define EPS    1e-12f

#define SZ3    (NB * C3 * HW)
#define SZ4    (NB * C4 * HW)
#define SZQ    (NB * CQ * HW)

// ---------------- scratch ----------------------------------------------------
__device__ __half g_Ah[(size_t)NB * HW * CK];     // norm q feats half K-major [b][m][k]
__device__ __half g_Bh[(size_t)NB * HW * CK];     // norm s feats half K-major [b][n][k]
__device__ __half g_attnH[(size_t)NB * HW * KP];  // UNNORMALIZED exp(logits) [b][q][s pad]
                                                  // (pad cols stay statically 0)
__device__ __half g_Vh[(size_t)NB * CQ * KP];     // f_s half                 [b][c][s pad]
__device__ float  g_psum[(size_t)NB * NTB * HW];  // per-nblock row sums      [b][nblk][q]
__device__ float  g_sum[(size_t)NB * HW];         // softmax denominators     [b][q]
__device__ float  g_attP[(size_t)NB * 2 * CQ * HW]; // split-K partials       [b*2+k][c][q]
__device__ float  g_nrm[16 * NB * HW];            // partial sumsq [sel4][quarter4][b][p]

__device__ __forceinline__ uint32_t smem_u32(const void* p) {
    uint32_t a;
    asm("{ .reg .u64 t; cvta.to.shared.u64 t, %1; cvt.u32.u64 %0, t; }" : "=r"(a) : "l"(p));
    return a;
}
__device__ __forceinline__ void mma_f16(float* d, const uint32_t* a, const uint32_t* b) {
    asm volatile(
        "mma.sync.aligned.m16n8k16.row.col.f32.f16.f16.f32 "
        "{%0,%1,%2,%3}, {%4,%5,%6,%7}, {%8,%9}, {%0,%1,%2,%3};"
        : "+f"(d[0]), "+f"(d[1]), "+f"(d[2]), "+f"(d[3])
        : "r"(a[0]), "r"(a[1]), "r"(a[2]), "r"(a[3]), "r"(b[0]), "r"(b[1]));
}

// ---------------- 1a) partial sum-of-squares, float4 along pixels -------------
__global__ void norms4_kernel(const float* __restrict__ inA,
                              const float* __restrict__ inB,
                              int Cf, int selbase) {
    int which = blockIdx.y;               // 0 = q tensor, 1 = s tensor
    const float* in = which ? inB : inA;
    int sel = selbase + which;
    int b   = blockIdx.x / 57;
    int p0  = (blockIdx.x % 57) * 64;
    int cq  = blockIdx.z;                 // channel quarter 0..3
    int Cq  = Cf >> 2;
    int tid = threadIdx.x;
    int px4 = tid & 15;
    int cg  = tid >> 4;
    bool pv = (p0 + 4 * px4 + 3 < HW);

    float4 a = make_float4(0.f, 0.f, 0.f, 0.f);
    if (pv) {
        const float* base = in + ((size_t)b * Cf + (size_t)cq * Cq) * HW + p0 + 4 * px4;
        #pragma unroll 4
        for (int c = cg; c < Cq; c += 16) {
            float4 x = *(const float4*)(base + (size_t)c * HW);
            a.x += x.x * x.x; a.y += x.y * x.y; a.z += x.z * x.z; a.w += x.w * x.w;
        }
    }
    __shared__ float part[16][64];
    part[cg][4 * px4 + 0] = a.x;
    part[cg][4 * px4 + 1] = a.y;
    part[cg][4 * px4 + 2] = a.z;
    part[cg][4 * px4 + 3] = a.w;
    __syncthreads();
    if (tid < 64 && p0 + tid < HW) {
        float t = 0.f;
        #pragma unroll
        for (int g = 0; g < 16; g++) t += part[g][tid];
        g_nrm[(((size_t)sel * 4 + cq) * NB + b) * HW + p0 + tid] = t;
    }
}

// ---------------- 1b) scale + transpose + half into K-major ------------------
__global__ void transpose_kernel(const float* __restrict__ in, int Cf, int coff,
                                 int sel /*0=A 1=B*/, int nsel) {
    __shared__ __half sh[32][66];
    int b  = blockIdx.z;
    int c0 = blockIdx.y * 64;
    int p0 = blockIdx.x * 32;
    int tid = threadIdx.x;
    int tx = tid & 31, ty = tid >> 5;       // ty 0..7

    int p = p0 + tx;
    bool pv = (p < HW);
    float inv = 0.f;
    if (pv) {
        size_t nb = ((size_t)nsel * 4 * NB + b) * HW + p;
        float s = g_nrm[nb] + g_nrm[nb + (size_t)NB * HW]
                + g_nrm[nb + (size_t)2 * NB * HW] + g_nrm[nb + (size_t)3 * NB * HW];
        inv = 1.f / fmaxf(sqrtf(s), EPS);
    }
    const float* X = in + ((size_t)b * Cf + c0) * HW + p;
    #pragma unroll
    for (int j = 0; j < 8; j++) {
        int c = ty * 8 + j;
        float v = pv ? X[(size_t)c * HW] : 0.f;
        sh[tx][c] = __float2half_rn(v * inv);
    }
    __syncthreads();
    __half* T = (sel ? g_Bh : g_Ah) + (size_t)b * HW * CK + coff + c0;
    #pragma unroll
    for (int k = 0; k < 4; k++) {
        int e  = tid + k * 256;
        int pr = e >> 5;
        int ln = e & 31;
        if (p0 + pr < HW) {
            uint32_t w = *(const uint32_t*)&sh[pr][2 * ln];
            *(uint32_t*)&T[(size_t)(p0 + pr) * CK + 2 * ln] = w;
        }
    }
}

// ---------------- 2a) corr GEMM + fused exp + partial row sums ---------------
// attnH[q][s] = exp(10 * sum_k A[q][k]*B[s][k]);  psum[b][nblk][q] = row sums.
// Logits bounded in [-10,10] -> exp is safe without max subtraction.
#define SROW_H  72
#define ROW_B   144
#define STG_B   (256 * ROW_B)              // 36864 B
#define GEMM_SMEM (2 * STG_B)              // 73728 B -> 2 CTAs/SM

__global__ __launch_bounds__(256, 2)
void corr_gemm(const __half* __restrict__ Aall, const __half* __restrict__ Ball,
               __half* __restrict__ Eall, float* __restrict__ psum) {
    extern __shared__ __align__(16) char smh[];
    __shared__ float rs[128];
    uint32_t sbase = smem_u32(smh);
    int tid = threadIdx.x;
    int wid = tid >> 5, lane = tid & 31;
    int grp = lane >> 2, tig = lane & 3;
    int wm = (wid & 3) * 32;
    int wn = (wid >> 2) * 64;
    int b  = blockIdx.z;
    int m0 = blockIdx.y * 128;
    int n0 = blockIdx.x * 128;
    const __half* A = Aall + (size_t)b * HW * CK;
    const __half* B = Ball + (size_t)b * HW * CK;

    float acc[2][8][4];
    #pragma unroll
    for (int mi = 0; mi < 2; mi++)
        #pragma unroll
        for (int ni = 0; ni < 8; ni++)
            #pragma unroll
            for (int j = 0; j < 4; j++) acc[mi][ni][j] = 0.f;

    auto load_tile = [&](int iter, int s) {
        int k0 = iter * 64;
        uint32_t stA = sbase + s * STG_B;
        #pragma unroll
        for (int j = 0; j < 4; j++) {
            int f = tid + j * 256;
            int row = f >> 3, q = f & 7;
            uint32_t nb = (m0 + row < HW) ? 16u : 0u;
            const __half* gp = A + (size_t)(nb ? m0 + row : 0) * CK + k0 + q * 8;
            uint32_t sa = stA + row * ROW_B + q * 16;
            asm volatile("cp.async.cg.shared.global [%0], [%1], 16, %2;"
                         :: "r"(sa), "l"(gp), "r"(nb) : "memory");
        }
        #pragma unroll
        for (int j = 0; j < 4; j++) {
            int f = tid + j * 256;
            int row = f >> 3, q = f & 7;
            uint32_t nb = (n0 + row < HW) ? 16u : 0u;
            const __half* gp = B + (size_t)(nb ? n0 + row : 0) * CK + k0 + q * 8;
            uint32_t sa = stA + 128 * ROW_B + row * ROW_B + q * 16;
            asm volatile("cp.async.cg.shared.global [%0], [%1], 16, %2;"
                         :: "r"(sa), "l"(gp), "r"(nb) : "memory");
        }
        asm volatile("cp.async.commit_group;" ::: "memory");
    };

    const int NIT = CK / 64;   // 48
    load_tile(0, 0);
    load_tile(1, 1);

    for (int i = 0; i < NIT; i++) {
        int s = i & 1;
        if (i + 1 < NIT) { asm volatile("cp.async.wait_group 1;" ::: "memory"); }
        else            { asm volatile("cp.async.wait_group 0;" ::: "memory"); }
        __syncthreads();

        const __half* as = (const __half*)(smh + (size_t)s * STG_B);
        const __half* bs = as + 128 * SROW_H;
        #pragma unroll
        for (int ks = 0; ks < 4; ks++) {
            int kk = ks * 16;
            uint32_t af[2][4];
            #pragma unroll
            for (int mi = 0; mi < 2; mi++) {
                int r = wm + mi * 16 + grp;
                af[mi][0] = *(const uint32_t*)&as[r * SROW_H + kk + 2 * tig];
                af[mi][1] = *(const uint32_t*)&as[(r + 8) * SROW_H + kk + 2 * tig];
                af[mi][2] = *(const uint32_t*)&as[r * SROW_H + kk + 8 + 2 * tig];
                af[mi][3] = *(const uint32_t*)&as[(r + 8) * SROW_H + kk + 8 + 2 * tig];
            }
            uint32_t bf[8][2];
            #pragma unroll
            for (int ni = 0; ni < 8; ni++) {
                int r = wn + ni * 8 + grp;
                bf[ni][0] = *(const uint32_t*)&bs[r * SROW_H + kk + 2 * tig];
                bf[ni][1] = *(const uint32_t*)&bs[r * SROW_H + kk + 8 + 2 * tig];
            }
            #pragma unroll
            for (int mi = 0; mi < 2; mi++)
                #pragma unroll
                for (int ni = 0; ni < 8; ni++)
                    mma_f16(acc[mi][ni], af[mi], bf[ni]);
        }
        __syncthreads();
        if (i + 2 < NIT) load_tile(i + 2, s);
    }

    // ---- fused exp epilogue + deterministic row-sum partials ----------------
    float rsum[2][2] = {{0.f, 0.f}, {0.f, 0.f}};
    #pragma unroll
    for (int mi = 0; mi < 2; mi++) {
        int r = m0 + wm + mi * 16 + grp;
        #pragma unroll
        for (int ni = 0; ni < 8; ni++) {
            int n = n0 + wn + ni * 8 + 2 * tig;
            bool nv = (n < HW);
            float e0 = nv ? expf(10.f * acc[mi][ni][0]) : 0.f;
            float e1 = nv ? expf(10.f * acc[mi][ni][1]) : 0.f;
            float e2 = nv ? expf(10.f * acc[mi][ni][2]) : 0.f;
            float e3 = nv ? expf(10.f * acc[mi][ni][3]) : 0.f;
            rsum[mi][0] += e0 + e1;
            rsum[mi][1] += e2 + e3;
            if (nv) {
                if (r < HW)
                    *(__half2*)&Eall[((size_t)b * HW + r) * KP + n] = __floats2half2_rn(e0, e1);
                if (r + 8 < HW)
                    *(__half2*)&Eall[((size_t)b * HW + r + 8) * KP + n] = __floats2half2_rn(e2, e3);
            }
        }
    }
    // reduce over the 4 tig lanes of each quad
    #pragma unroll
    for (int mi = 0; mi < 2; mi++)
        #pragma unroll
        for (int h = 0; h < 2; h++) {
            rsum[mi][h] += __shfl_xor_sync(0xffffffffu, rsum[mi][h], 1);
            rsum[mi][h] += __shfl_xor_sync(0xffffffffu, rsum[mi][h], 2);
        }
    __syncthreads();              // smem tile reuse barrier
    if (tig == 0 && wid < 4) {
        #pragma unroll
        for (int mi = 0; mi < 2; mi++)
            #pragma unroll
            for (int h = 0; h < 2; h++)
                rs[wm + mi * 16 + grp + h * 8] = rsum[mi][h];
    }
    __syncthreads();
    if (tig == 0 && wid >= 4) {
        #pragma unroll
        for (int mi = 0; mi < 2; mi++)
            #pragma unroll
            for (int h = 0; h < 2; h++)
                rs[wm + mi * 16 + grp + h * 8] += rsum[mi][h];
    }
    __syncthreads();
    if (tid < 128) {
        int m = m0 + tid;
        if (m < HW)
            psum[((size_t)b * NTB + blockIdx.x) * HW + m] = rs[tid];
    }
}

// ---------------- 2b) denominator reduce: g_sum[b][q] = sum_nblk psum --------
__global__ void sumred_kernel() {
    int idx = blockIdx.x * blockDim.x + threadIdx.x;
    if (idx >= NB * HW) return;
    int b = idx / HW, q = idx % HW;
    float s = 0.f;
    #pragma unroll
    for (int t = 0; t < NTB; t++)
        s += g_psum[((size_t)b * NTB + t) * HW + q];
    g_sum[idx] = s;
}

// ---------------- 2c) attn GEMM: 128x128, split-K ----------------------------
__global__ __launch_bounds__(256, 2)
void gemm_h(const __half* __restrict__ Aall, const __half* __restrict__ Ball,
            float* __restrict__ Call, int ldk, int nIter, int Mg, int Ng,
            size_t strideA, size_t strideB, size_t strideC, int nSplit) {
    extern __shared__ __align__(16) char smh[];
    uint32_t sbase = smem_u32(smh);
    int tid = threadIdx.x;
    int wid = tid >> 5, lane = tid & 31;
    int grp = lane >> 2, tig = lane & 3;
    int wm = (wid & 3) * 32;
    int wn = (wid >> 2) * 64;
    int z   = blockIdx.z;
    int b   = z / nSplit;
    int ksp = z - b * nSplit;
    int m0 = blockIdx.y * 128;
    int n0 = blockIdx.x * 128;
    const __half* A = Aall + (size_t)b * strideA;
    const __half* B = Ball + (size_t)b * strideB;
    float* Cb = Call + (size_t)z * strideC;

    int per = (nIter + nSplit - 1) / nSplit;
    int i0  = ksp * per;
    int i1  = min(nIter, i0 + per);

    float acc[2][8][4];
    #pragma unroll
    for (int mi = 0; mi < 2; mi++)
        #pragma unroll
        for (int ni = 0; ni < 8; ni++)
            #pragma unroll
            for (int j = 0; j < 4; j++) acc[mi][ni][j] = 0.f;

    auto load_tile = [&](int iter, int s) {
        int k0 = iter * 64;
        uint32_t stA = sbase + s * STG_B;
        #pragma unroll
        for (int j = 0; j < 4; j++) {
            int f = tid + j * 256;
            int row = f >> 3, q = f & 7;
            uint32_t nb = (m0 + row < Mg) ? 16u : 0u;
            const __half* gp = A + (size_t)(nb ? m0 + row : 0) * ldk + k0 + q * 8;
            uint32_t sa = stA + row * ROW_B + q * 16;
            asm volatile("cp.async.cg.shared.global [%0], [%1], 16, %2;"
                         :: "r"(sa), "l"(gp), "r"(nb) : "memory");
        }
        #pragma unroll
        for (int j = 0; j < 4; j++) {
            int f = tid + j * 256;
            int row = f >> 3, q = f & 7;
            uint32_t nb = (n0 + row < Ng) ? 16u : 0u;
            const __half* gp = B + (size_t)(nb ? n0 + row : 0) * ldk + k0 + q * 8;
            uint32_t sa = stA + 128 * ROW_B + row * ROW_B + q * 16;
            asm volatile("cp.async.cg.shared.global [%0], [%1], 16, %2;"
                         :: "r"(sa), "l"(gp), "r"(nb) : "memory");
        }
        asm volatile("cp.async.commit_group;" ::: "memory");
    };

    load_tile(i0, 0);
    if (i0 + 1 < i1) load_tile(i0 + 1, 1);

    for (int i = i0; i < i1; i++) {
        int s = (i - i0) & 1;
        if (i + 1 < i1) { asm volatile("cp.async.wait_group 1;" ::: "memory"); }
        else           { asm volatile("cp.async.wait_group 0;" ::: "memory"); }
        __syncthreads();

        const __half* as = (const __half*)(smh + (size_t)s * STG_B);
        const __half* bs = as + 128 * SROW_H;
        #pragma unroll
        for (int ks = 0; ks < 4; ks++) {
            int kk = ks * 16;
            uint32_t af[2][4];
            #pragma unroll
            for (int mi = 0; mi < 2; mi++) {
                int r = wm + mi * 16 + grp;
                af[mi][0] = *(const uint32_t*)&as[r * SROW_H + kk + 2 * tig];
                af[mi][1] = *(const uint32_t*)&as[(r + 8) * SROW_H + kk + 2 * tig];
                af[mi][2] = *(const uint32_t*)&as[r * SROW_H + kk + 8 + 2 * tig];
                af[mi][3] = *(const uint32_t*)&as[(r + 8) * SROW_H + kk + 8 + 2 * tig];
            }
            uint32_t bf[8][2];
            #pragma unroll
            for (int ni = 0; ni < 8; ni++) {
                int r = wn + ni * 8 + grp;
                bf[ni][0] = *(const uint32_t*)&bs[r * SROW_H + kk + 2 * tig];
                bf[ni][1] = *(const uint32_t*)&bs[r * SROW_H + kk + 8 + 2 * tig];
            }
            #pragma unroll
            for (int mi = 0; mi < 2; mi++)
                #pragma unroll
                for (int ni = 0; ni < 8; ni++)
                    mma_f16(acc[mi][ni], af[mi], bf[ni]);
        }
        __syncthreads();
        if (i + 2 < i1) load_tile(i + 2, s);
    }

    #pragma unroll
    for (int mi = 0; mi < 2; mi++) {
        int mrow = m0 + wm + mi * 16 + grp;
        #pragma unroll
        for (int ni = 0; ni < 8; ni++) {
            int n = n0 + wn + ni * 8 + 2 * tig;
            if (n < Ng) {
                if (mrow < Mg)
                    *(float2*)&Cb[(size_t)mrow * HW + n] =
                        make_float2(acc[mi][ni][0], acc[mi][ni][1]);
                if (mrow + 8 < Mg)
                    *(float2*)&Cb[(size_t)(mrow + 8) * HW + n] =
                        make_float2(acc[mi][ni][2], acc[mi][ni][3]);
            }
        }
    }
}

// ---------------- 3) f_s -> half, K-padded ------------------------------------
__global__ void vprep_kernel(const float* __restrict__ V) {
    int idx = blockIdx.x * blockDim.x + threadIdx.x;
    if (idx >= NB * CQ * KP) return;
    int s = idx % KP;
    int bc = idx / KP;
    g_Vh[idx] = __float2half_rn(s < HW ? V[(size_t)bc * HW + s] : 0.f);
}

// ---------------- 4) combine: split-K reduce + softmax denom + outputs -------
// y = unnormalized exp @ V; true att = y / sum[q]; l2norm is scale-invariant.
__global__ void combine_kernel(const float* __restrict__ f_q,
                               float* __restrict__ out_fq,
                               float* __restrict__ out_att, int writeAtt) {
    int idx = blockIdx.x * blockDim.x + threadIdx.x;
    if (idx >= NB * HW) return;
    int b = idx / HW, p = idx % HW;
    const float* qb = f_q + (size_t)b * CQ * HW + p;
    const float* a0 = g_attP + ((size_t)2 * b) * CQ * HW + p;
    const float* a1 = g_attP + ((size_t)2 * b + 1) * CQ * HW + p;
    float rs = 1.f / g_sum[idx];
    float sq = 0.f, sa = 0.f;
    #pragma unroll 8
    for (int c = 0; c < CQ; c++) {
        float x = qb[(size_t)c * HW]; sq += x * x;
        float y = a0[(size_t)c * HW] + a1[(size_t)c * HW]; sa += y * y;
    }
    float iq = 1.f / fmaxf(sqrtf(sq), EPS);
    float ia = ATT_WT / fmaxf(sqrtf(sa), EPS);   // scale of y cancels in l2norm
    float* ob = out_fq + (size_t)b * CQ * HW + p;
    if (writeAtt) {
        float* oa = out_att + (size_t)b * CQ * HW + p;
        #pragma unroll 4
        for (int c = 0; c < CQ; c++) {
            float y = a0[(size_t)c * HW] + a1[(size_t)c * HW];
            ob[(size_t)c * HW] = qb[(size_t)c * HW] * iq + y * ia;
            oa[(size_t)c * HW] = y * rs;
        }
    } else {
        #pragma unroll 4
        for (int c = 0; c < CQ; c++) {
            float y = a0[(size_t)c * HW] + a1[(size_t)c * HW];
            ob[(size_t)c * HW] = qb[(size_t)c * HW] * iq + y * ia;
        }
    }
}

// ---------------- launch ------------------------------------------------------
extern "C" void kernel_launch(void* const* d_in, const int* in_sizes, int n_in,
                              void* d_out, int out_size) {
    const float *fq3 = 0, *fs3 = 0, *fq4 = 0, *fs4 = 0, *f_q = 0, *f_s = 0;
    for (int i = 0; i < n_in; i++) {
        const float* p = (const float*)d_in[i];
        int sz = in_sizes[i];
        if (sz == SZ3)      { if (!fq3) fq3 = p; else fs3 = p; }
        else if (sz == SZ4) { if (!fq4) fq4 = p; else fs4 = p; }
        else if (sz == SZQ) { if (!f_q) f_q = p; else f_s = p; }
    }
    float* out = (float*)d_out;

    // TRUE device addresses (host shadow symbols are ATS-dereferenceable on
    // GB300 -> silent zero-data bug if passed directly).
    void *pAh, *pBh, *pAttnH, *pVh, *pAttP, *pPsum;
    cudaGetSymbolAddress(&pAh, g_Ah);
    cudaGetSymbolAddress(&pBh, g_Bh);
    cudaGetSymbolAddress(&pAttnH, g_attnH);
    cudaGetSymbolAddress(&pVh, g_Vh);
    cudaGetSymbolAddress(&pAttP, g_attP);
    cudaGetSymbolAddress(&pPsum, g_psum);

    cudaFuncSetAttribute(corr_gemm, cudaFuncAttributeMaxDynamicSharedMemorySize, GEMM_SMEM);
    cudaFuncSetAttribute(gemm_h, cudaFuncAttributeMaxDynamicSharedMemorySize, GEMM_SMEM);

    norms4_kernel<<<dim3(114, 2, 4), 256>>>(fq4, fs4, C4, 0);
    norms4_kernel<<<dim3(114, 2, 4), 256>>>(fq3, fs3, C3, 2);

    transpose_kernel<<<dim3(113, C4 / 64, NB), 256>>>(fq4, C4, 0,  0, 0);
    transpose_kernel<<<dim3(113, C4 / 64, NB), 256>>>(fs4, C4, 0,  1, 1);
    transpose_kernel<<<dim3(113, C3 / 64, NB), 256>>>(fq3, C3, C4, 0, 2);
    transpose_kernel<<<dim3(113, C3 / 64, NB), 256>>>(fs3, C3, C4, 1, 3);

    vprep_kernel<<<(NB * CQ * KP + 255) / 256, 256>>>(f_s);

    // corr GEMM with fused exp(10*logit) epilogue -> attnH (half) + psum
    corr_gemm<<<dim3(NTB, NTB, NB), 256, GEMM_SMEM>>>(
        (const __half*)pAh, (const __half*)pBh, (__half*)pAttnH, (float*)pPsum);

    sumred_kernel<<<(NB * HW + 255) / 256, 256>>>();

    // attn GEMM with split-K=2: partials into g_attP (reduced inside combine)
    gemm_h<<<dim3(29, 2, NB * 2), 256, GEMM_SMEM>>>(
        (const __half*)pVh, (const __half*)pAttnH, (float*)pAttP,
        KP, KP / 64, CQ, HW,
        (size_t)CQ * KP, (size_t)HW * KP, (size_t)CQ * HW, 2);

    int writeAtt = (out_size >= 2 * SZQ) ? 1 : 0;
    combine_kernel<<<29, 256>>>(f_q, out, out + SZQ, writeAtt);
}

// round 14
// speedup vs baseline: 1.1996x; 1.0442x over previous
#include <cuda_runtime.h>
#include <cuda_fp16.h>
#include <cstdint>
#include <math.h>

#define HW     3600
#define NB     2
#define CK     3072      // 2048 + 1024 stacked channels
#define C4     2048
#define C3     1024
#define CQ     256
#define KP     3648      // HW padded for attn GEMM K dim
#define NTB    29        // n-tile blocks in corr GEMM (29*128 >= 3600)
#define ATT_WT 0.5f
#define EPS    1e-12f

#define SZ3    (NB * C3 * HW)
#define SZ4    (NB * C4 * HW)
#define SZQ    (NB * CQ * HW)

// ---------------- scratch ----------------------------------------------------
__device__ __half g_Ah[(size_t)NB * HW * CK];     // norm q feats half K-major [b][m][k]
__device__ __half g_Bh[(size_t)NB * HW * CK];     // norm s feats half K-major [b][n][k]
__device__ __half g_attnH[(size_t)NB * HW * KP];  // UNNORMALIZED exp(logits) [b][q][s pad]
__device__ __half g_Vh[(size_t)NB * CQ * KP];     // f_s half                 [b][c][s pad]
__device__ float  g_psum[(size_t)NB * NTB * HW];  // per-nblock row sums      [b][nblk][q]
__device__ float  g_sum[(size_t)NB * HW];         // softmax denominators     [b][q]
__device__ float  g_attP[(size_t)NB * 2 * CQ * HW]; // split-K partials       [b*2+k][c][q]
__device__ float  g_nrm[16 * NB * HW];            // partial sumsq [sel4][quarter4][b][p]

__device__ __forceinline__ uint32_t smem_u32(const void* p) {
    uint32_t a;
    asm("{ .reg .u64 t; cvta.to.shared.u64 t, %1; cvt.u32.u64 %0, t; }" : "=r"(a) : "l"(p));
    return a;
}
__device__ __forceinline__ void mma_f16(float* d, const uint32_t* a, const uint32_t* b) {
    asm volatile(
        "mma.sync.aligned.m16n8k16.row.col.f32.f16.f16.f32 "
        "{%0,%1,%2,%3}, {%4,%5,%6,%7}, {%8,%9}, {%0,%1,%2,%3};"
        : "+f"(d[0]), "+f"(d[1]), "+f"(d[2]), "+f"(d[3])
        : "r"(a[0]), "r"(a[1]), "r"(a[2]), "r"(a[3]), "r"(b[0]), "r"(b[1]));
}

// ---------------- 1a) partial sum-of-squares, float4 along pixels -------------
__global__ void norms4_kernel(const float* __restrict__ inA,
                              const float* __restrict__ inB,
                              int Cf, int selbase) {
    int which = blockIdx.y;               // 0 = q tensor, 1 = s tensor
    const float* in = which ? inB : inA;
    int sel = selbase + which;
    int b   = blockIdx.x / 57;
    int p0  = (blockIdx.x % 57) * 64;
    int cq  = blockIdx.z;                 // channel quarter 0..3
    int Cq  = Cf >> 2;
    int tid = threadIdx.x;
    int px4 = tid & 15;
    int cg  = tid >> 4;
    bool pv = (p0 + 4 * px4 + 3 < HW);

    float4 a = make_float4(0.f, 0.f, 0.f, 0.f);
    if (pv) {
        const float* base = in + ((size_t)b * Cf + (size_t)cq * Cq) * HW + p0 + 4 * px4;
        #pragma unroll 4
        for (int c = cg; c < Cq; c += 16) {
            float4 x = *(const float4*)(base + (size_t)c * HW);
            a.x += x.x * x.x; a.y += x.y * x.y; a.z += x.z * x.z; a.w += x.w * x.w;
        }
    }
    __shared__ float part[16][64];
    part[cg][4 * px4 + 0] = a.x;
    part[cg][4 * px4 + 1] = a.y;
    part[cg][4 * px4 + 2] = a.z;
    part[cg][4 * px4 + 3] = a.w;
    __syncthreads();
    if (tid < 64 && p0 + tid < HW) {
        float t = 0.f;
        #pragma unroll
        for (int g = 0; g < 16; g++) t += part[g][tid];
        g_nrm[(((size_t)sel * 4 + cq) * NB + b) * HW + p0 + tid] = t;
    }
}

// ---------------- 1b) scale + transpose + half into K-major ------------------
// grid.z = b*2 + which (q/s fused into one launch)
__global__ void transpose_kernel(const float* __restrict__ inA,
                                 const float* __restrict__ inB,
                                 int Cf, int coff, int selbase) {
    __shared__ __half sh[32][66];
    int z  = blockIdx.z;
    int b  = z >> 1;
    int which = z & 1;                     // 0 = q (->g_Ah), 1 = s (->g_Bh)
    const float* in = which ? inB : inA;
    int nsel = selbase + which;
    int c0 = blockIdx.y * 64;
    int p0 = blockIdx.x * 32;
    int tid = threadIdx.x;
    int tx = tid & 31, ty = tid >> 5;       // ty 0..7

    int p = p0 + tx;
    bool pv = (p < HW);
    float inv = 0.f;
    if (pv) {
        size_t nb = ((size_t)nsel * 4 * NB + b) * HW + p;
        float s = g_nrm[nb] + g_nrm[nb + (size_t)NB * HW]
                + g_nrm[nb + (size_t)2 * NB * HW] + g_nrm[nb + (size_t)3 * NB * HW];
        inv = 1.f / fmaxf(sqrtf(s), EPS);
    }
    const float* X = in + ((size_t)b * Cf + c0) * HW + p;
    #pragma unroll
    for (int j = 0; j < 8; j++) {
        int c = ty * 8 + j;
        float v = pv ? X[(size_t)c * HW] : 0.f;
        sh[tx][c] = __float2half_rn(v * inv);
    }
    __syncthreads();
    __half* T = (which ? g_Bh : g_Ah) + (size_t)b * HW * CK + coff + c0;
    #pragma unroll
    for (int k = 0; k < 4; k++) {
        int e  = tid + k * 256;
        int pr = e >> 5;
        int ln = e & 31;
        if (p0 + pr < HW) {
            uint32_t w = *(const uint32_t*)&sh[pr][2 * ln];
            *(uint32_t*)&T[(size_t)(p0 + pr) * CK + 2 * ln] = w;
        }
    }
}

// ---------------- 2a) corr GEMM + fused exp + partial row sums ---------------
// attnH[q][s] = exp(10 * cos);  logits in [-10,10] -> exp safe, no max needed.
#define SROW_H  72
#define ROW_B   144
#define STG_B   (256 * ROW_B)              // 36864 B
#define GEMM_SMEM (2 * STG_B)              // 73728 B -> 2 CTAs/SM

__global__ __launch_bounds__(256, 2)
void corr_gemm(const __half* __restrict__ Aall, const __half* __restrict__ Ball,
               __half* __restrict__ Eall, float* __restrict__ psum) {
    extern __shared__ __align__(16) char smh[];
    __shared__ float rs[128];
    uint32_t sbase = smem_u32(smh);
    int tid = threadIdx.x;
    int wid = tid >> 5, lane = tid & 31;
    int grp = lane >> 2, tig = lane & 3;
    int wm = (wid & 3) * 32;
    int wn = (wid >> 2) * 64;
    int b  = blockIdx.z;
    int m0 = blockIdx.y * 128;
    int n0 = blockIdx.x * 128;
    const __half* A = Aall + (size_t)b * HW * CK;
    const __half* B = Ball + (size_t)b * HW * CK;

    float acc[2][8][4];
    #pragma unroll
    for (int mi = 0; mi < 2; mi++)
        #pragma unroll
        for (int ni = 0; ni < 8; ni++)
            #pragma unroll
            for (int j = 0; j < 4; j++) acc[mi][ni][j] = 0.f;

    auto load_tile = [&](int iter, int s) {
        int k0 = iter * 64;
        uint32_t stA = sbase + s * STG_B;
        #pragma unroll
        for (int j = 0; j < 4; j++) {
            int f = tid + j * 256;
            int row = f >> 3, q = f & 7;
            uint32_t nb = (m0 + row < HW) ? 16u : 0u;
            const __half* gp = A + (size_t)(nb ? m0 + row : 0) * CK + k0 + q * 8;
            uint32_t sa = stA + row * ROW_B + q * 16;
            asm volatile("cp.async.cg.shared.global [%0], [%1], 16, %2;"
                         :: "r"(sa), "l"(gp), "r"(nb) : "memory");
        }
        #pragma unroll
        for (int j = 0; j < 4; j++) {
            int f = tid + j * 256;
            int row = f >> 3, q = f & 7;
            uint32_t nb = (n0 + row < HW) ? 16u : 0u;
            const __half* gp = B + (size_t)(nb ? n0 + row : 0) * CK + k0 + q * 8;
            uint32_t sa = stA + 128 * ROW_B + row * ROW_B + q * 16;
            asm volatile("cp.async.cg.shared.global [%0], [%1], 16, %2;"
                         :: "r"(sa), "l"(gp), "r"(nb) : "memory");
        }
        asm volatile("cp.async.commit_group;" ::: "memory");
    };

    const int NIT = CK / 64;   // 48
    load_tile(0, 0);
    load_tile(1, 1);

    for (int i = 0; i < NIT; i++) {
        int s = i & 1;
        if (i + 1 < NIT) { asm volatile("cp.async.wait_group 1;" ::: "memory"); }
        else            { asm volatile("cp.async.wait_group 0;" ::: "memory"); }
        __syncthreads();

        const __half* as = (const __half*)(smh + (size_t)s * STG_B);
        const __half* bs = as + 128 * SROW_H;
        #pragma unroll
        for (int ks = 0; ks < 4; ks++) {
            int kk = ks * 16;
            uint32_t af[2][4];
            #pragma unroll
            for (int mi = 0; mi < 2; mi++) {
                int r = wm + mi * 16 + grp;
                af[mi][0] = *(const uint32_t*)&as[r * SROW_H + kk + 2 * tig];
                af[mi][1] = *(const uint32_t*)&as[(r + 8) * SROW_H + kk + 2 * tig];
                af[mi][2] = *(const uint32_t*)&as[r * SROW_H + kk + 8 + 2 * tig];
                af[mi][3] = *(const uint32_t*)&as[(r + 8) * SROW_H + kk + 8 + 2 * tig];
            }
            uint32_t bf[8][2];
            #pragma unroll
            for (int ni = 0; ni < 8; ni++) {
                int r = wn + ni * 8 + grp;
                bf[ni][0] = *(const uint32_t*)&bs[r * SROW_H + kk + 2 * tig];
                bf[ni][1] = *(const uint32_t*)&bs[r * SROW_H + kk + 8 + 2 * tig];
            }
            #pragma unroll
            for (int mi = 0; mi < 2; mi++)
                #pragma unroll
                for (int ni = 0; ni < 8; ni++)
                    mma_f16(acc[mi][ni], af[mi], bf[ni]);
        }
        __syncthreads();
        if (i + 2 < NIT) load_tile(i + 2, s);
    }

    // ---- fused fast-exp epilogue + deterministic row-sum partials ------------
    float rsum[2][2] = {{0.f, 0.f}, {0.f, 0.f}};
    #pragma unroll
    for (int mi = 0; mi < 2; mi++) {
        int r = m0 + wm + mi * 16 + grp;
        #pragma unroll
        for (int ni = 0; ni < 8; ni++) {
            int n = n0 + wn + ni * 8 + 2 * tig;
            bool nv = (n < HW);
            float e0 = nv ? __expf(10.f * acc[mi][ni][0]) : 0.f;
            float e1 = nv ? __expf(10.f * acc[mi][ni][1]) : 0.f;
            float e2 = nv ? __expf(10.f * acc[mi][ni][2]) : 0.f;
            float e3 = nv ? __expf(10.f * acc[mi][ni][3]) : 0.f;
            rsum[mi][0] += e0 + e1;
            rsum[mi][1] += e2 + e3;
            if (nv) {
                if (r < HW)
                    *(__half2*)&Eall[((size_t)b * HW + r) * KP + n] = __floats2half2_rn(e0, e1);
                if (r + 8 < HW)
                    *(__half2*)&Eall[((size_t)b * HW + r + 8) * KP + n] = __floats2half2_rn(e2, e3);
            }
        }
    }
    #pragma unroll
    for (int mi = 0; mi < 2; mi++)
        #pragma unroll
        for (int h = 0; h < 2; h++) {
            rsum[mi][h] += __shfl_xor_sync(0xffffffffu, rsum[mi][h], 1);
            rsum[mi][h] += __shfl_xor_sync(0xffffffffu, rsum[mi][h], 2);
        }
    __syncthreads();
    if (tig == 0 && wid < 4) {
        #pragma unroll
        for (int mi = 0; mi < 2; mi++)
            #pragma unroll
            for (int h = 0; h < 2; h++)
                rs[wm + mi * 16 + grp + h * 8] = rsum[mi][h];
    }
    __syncthreads();
    if (tig == 0 && wid >= 4) {
        #pragma unroll
        for (int mi = 0; mi < 2; mi++)
            #pragma unroll
            for (int h = 0; h < 2; h++)
                rs[wm + mi * 16 + grp + h * 8] += rsum[mi][h];
    }
    __syncthreads();
    if (tid < 128) {
        int m = m0 + tid;
        if (m < HW)
            psum[((size_t)b * NTB + blockIdx.x) * HW + m] = rs[tid];
    }
}

// ---------------- 2b) denominator reduce: g_sum[b][q] = sum_nblk psum --------
__global__ void sumred_kernel() {
    int idx = blockIdx.x * blockDim.x + threadIdx.x;
    if (idx >= NB * HW) return;
    int b = idx / HW, q = idx % HW;
    float s = 0.f;
    #pragma unroll
    for (int t = 0; t < NTB; t++)
        s += g_psum[((size_t)b * NTB + t) * HW + q];
    g_sum[idx] = s;
}

// ---------------- 2c) attn GEMM: 128x128, split-K ----------------------------
__global__ __launch_bounds__(256, 2)
void gemm_h(const __half* __restrict__ Aall, const __half* __restrict__ Ball,
            float* __restrict__ Call, int ldk, int nIter, int Mg, int Ng,
            size_t strideA, size_t strideB, size_t strideC, int nSplit) {
    extern __shared__ __align__(16) char smh[];
    uint32_t sbase = smem_u32(smh);
    int tid = threadIdx.x;
    int wid = tid >> 5, lane = tid & 31;
    int grp = lane >> 2, tig = lane & 3;
    int wm = (wid & 3) * 32;
    int wn = (wid >> 2) * 64;
    int z   = blockIdx.z;
    int b   = z / nSplit;
    int ksp = z - b * nSplit;
    int m0 = blockIdx.y * 128;
    int n0 = blockIdx.x * 128;
    const __half* A = Aall + (size_t)b * strideA;
    const __half* B = Ball + (size_t)b * strideB;
    float* Cb = Call + (size_t)z * strideC;

    int per = (nIter + nSplit - 1) / nSplit;
    int i0  = ksp * per;
    int i1  = min(nIter, i0 + per);

    float acc[2][8][4];
    #pragma unroll
    for (int mi = 0; mi < 2; mi++)
        #pragma unroll
        for (int ni = 0; ni < 8; ni++)
            #pragma unroll
            for (int j = 0; j < 4; j++) acc[mi][ni][j] = 0.f;

    auto load_tile = [&](int iter, int s) {
        int k0 = iter * 64;
        uint32_t stA = sbase + s * STG_B;
        #pragma unroll
        for (int j = 0; j < 4; j++) {
            int f = tid + j * 256;
            int row = f >> 3, q = f & 7;
            uint32_t nb = (m0 + row < Mg) ? 16u : 0u;
            const __half* gp = A + (size_t)(nb ? m0 + row : 0) * ldk + k0 + q * 8;
            uint32_t sa = stA + row * ROW_B + q * 16;
            asm volatile("cp.async.cg.shared.global [%0], [%1], 16, %2;"
                         :: "r"(sa), "l"(gp), "r"(nb) : "memory");
        }
        #pragma unroll
        for (int j = 0; j < 4; j++) {
            int f = tid + j * 256;
            int row = f >> 3, q = f & 7;
            uint32_t nb = (n0 + row < Ng) ? 16u : 0u;
            const __half* gp = B + (size_t)(nb ? n0 + row : 0) * ldk + k0 + q * 8;
            uint32_t sa = stA + 128 * ROW_B + row * ROW_B + q * 16;
            asm volatile("cp.async.cg.shared.global [%0], [%1], 16, %2;"
                         :: "r"(sa), "l"(gp), "r"(nb) : "memory");
        }
        asm volatile("cp.async.commit_group;" ::: "memory");
    };

    load_tile(i0, 0);
    if (i0 + 1 < i1) load_tile(i0 + 1, 1);

    for (int i = i0; i < i1; i++) {
        int s = (i - i0) & 1;
        if (i + 1 < i1) { asm volatile("cp.async.wait_group 1;" ::: "memory"); }
        else           { asm volatile("cp.async.wait_group 0;" ::: "memory"); }
        __syncthreads();

        const __half* as = (const __half*)(smh + (size_t)s * STG_B);
        const __half* bs = as + 128 * SROW_H;
        #pragma unroll
        for (int ks = 0; ks < 4; ks++) {
            int kk = ks * 16;
            uint32_t af[2][4];
            #pragma unroll
            for (int mi = 0; mi < 2; mi++) {
                int r = wm + mi * 16 + grp;
                af[mi][0] = *(const uint32_t*)&as[r * SROW_H + kk + 2 * tig];
                af[mi][1] = *(const uint32_t*)&as[(r + 8) * SROW_H + kk + 2 * tig];
                af[mi][2] = *(const uint32_t*)&as[r * SROW_H + kk + 8 + 2 * tig];
                af[mi][3] = *(const uint32_t*)&as[(r + 8) * SROW_H + kk + 8 + 2 * tig];
            }
            uint32_t bf[8][2];
            #pragma unroll
            for (int ni = 0; ni < 8; ni++) {
                int r = wn + ni * 8 + grp;
                bf[ni][0] = *(const uint32_t*)&bs[r * SROW_H + kk + 2 * tig];
                bf[ni][1] = *(const uint32_t*)&bs[r * SROW_H + kk + 8 + 2 * tig];
            }
            #pragma unroll
            for (int mi = 0; mi < 2; mi++)
                #pragma unroll
                for (int ni = 0; ni < 8; ni++)
                    mma_f16(acc[mi][ni], af[mi], bf[ni]);
        }
        __syncthreads();
        if (i + 2 < i1) load_tile(i + 2, s);
    }

    #pragma unroll
    for (int mi = 0; mi < 2; mi++) {
        int mrow = m0 + wm + mi * 16 + grp;
        #pragma unroll
        for (int ni = 0; ni < 8; ni++) {
            int n = n0 + wn + ni * 8 + 2 * tig;
            if (n < Ng) {
                if (mrow < Mg)
                    *(float2*)&Cb[(size_t)mrow * HW + n] =
                        make_float2(acc[mi][ni][0], acc[mi][ni][1]);
                if (mrow + 8 < Mg)
                    *(float2*)&Cb[(size_t)(mrow + 8) * HW + n] =
                        make_float2(acc[mi][ni][2], acc[mi][ni][3]);
            }
        }
    }
}

// ---------------- 3) f_s -> half, K-padded, vectorized ------------------------
__global__ void vprep_kernel(const float* __restrict__ V) {
    int idx = blockIdx.x * blockDim.x + threadIdx.x;
    if (idx >= NB * CQ * KP / 2) return;
    int s2 = idx % (KP / 2);
    int bc = idx / (KP / 2);
    int s  = 2 * s2;
    __half2 h;
    if (s + 1 < HW) {
        float2 v = *(const float2*)&V[(size_t)bc * HW + s];
        h = __floats2half2_rn(v.x, v.y);
    } else {
        h = __floats2half2_rn(0.f, 0.f);
    }
    *(__half2*)&g_Vh[(size_t)bc * KP + s] = h;
}

// ---------------- 4) combine: split-K reduce + denom + outputs ----------------
// block: 4 channel-groups x 64 pixels; grid: ceil(NB*HW/64) = 113
__global__ void combine_kernel(const float* __restrict__ f_q,
                               float* __restrict__ out_fq,
                               float* __restrict__ out_att, int writeAtt) {
    int tid = threadIdx.x;
    int cg  = tid >> 6;                    // 0..3
    int pl  = tid & 63;
    int gpix = blockIdx.x * 64 + pl;       // 0 .. NB*HW-1
    bool pv = (gpix < NB * HW);
    int b = pv ? gpix / HW : 0;
    int p = pv ? gpix % HW : 0;

    const float* qb = f_q + (size_t)b * CQ * HW + p;
    const float* a0 = g_attP + ((size_t)2 * b) * CQ * HW + p;
    const float* a1 = g_attP + ((size_t)2 * b + 1) * CQ * HW + p;

    float sq = 0.f, sa = 0.f;
    if (pv) {
        #pragma unroll 8
        for (int c = cg * 64; c < cg * 64 + 64; c++) {
            float x = qb[(size_t)c * HW]; sq += x * x;
            float y = a0[(size_t)c * HW] + a1[(size_t)c * HW]; sa += y * y;
        }
    }
    __shared__ float sQ[4][64], sA[4][64];
    sQ[cg][pl] = sq;
    sA[cg][pl] = sa;
    __syncthreads();
    float tq = sQ[0][pl] + sQ[1][pl] + sQ[2][pl] + sQ[3][pl];
    float ta = sA[0][pl] + sA[1][pl] + sA[2][pl] + sA[3][pl];
    float iq = 1.f / fmaxf(sqrtf(tq), EPS);
    float ia = ATT_WT / fmaxf(sqrtf(ta), EPS);   // scale of y cancels in l2norm
    float rs = pv ? (1.f / g_sum[gpix]) : 0.f;

    if (pv) {
        float* ob = out_fq + (size_t)b * CQ * HW + p;
        if (writeAtt) {
            float* oa = out_att + (size_t)b * CQ * HW + p;
            #pragma unroll 4
            for (int c = cg * 64; c < cg * 64 + 64; c++) {
                float y = a0[(size_t)c * HW] + a1[(size_t)c * HW];
                ob[(size_t)c * HW] = qb[(size_t)c * HW] * iq + y * ia;
                oa[(size_t)c * HW] = y * rs;
            }
        } else {
            #pragma unroll 4
            for (int c = cg * 64; c < cg * 64 + 64; c++) {
                float y = a0[(size_t)c * HW] + a1[(size_t)c * HW];
                ob[(size_t)c * HW] = qb[(size_t)c * HW] * iq + y * ia;
            }
        }
    }
}

// ---------------- launch ------------------------------------------------------
extern "C" void kernel_launch(void* const* d_in, const int* in_sizes, int n_in,
                              void* d_out, int out_size) {
    const float *fq3 = 0, *fs3 = 0, *fq4 = 0, *fs4 = 0, *f_q = 0, *f_s = 0;
    for (int i = 0; i < n_in; i++) {
        const float* p = (const float*)d_in[i];
        int sz = in_sizes[i];
        if (sz == SZ3)      { if (!fq3) fq3 = p; else fs3 = p; }
        else if (sz == SZ4) { if (!fq4) fq4 = p; else fs4 = p; }
        else if (sz == SZQ) { if (!f_q) f_q = p; else f_s = p; }
    }
    float* out = (float*)d_out;

    // TRUE device addresses (host shadow symbols are ATS-dereferenceable on
    // GB300 -> silent zero-data bug if passed directly).
    void *pAh, *pBh, *pAttnH, *pVh, *pAttP, *pPsum;
    cudaGetSymbolAddress(&pAh, g_Ah);
    cudaGetSymbolAddress(&pBh, g_Bh);
    cudaGetSymbolAddress(&pAttnH, g_attnH);
    cudaGetSymbolAddress(&pVh, g_Vh);
    cudaGetSymbolAddress(&pAttP, g_attP);
    cudaGetSymbolAddress(&pPsum, g_psum);

    cudaFuncSetAttribute(corr_gemm, cudaFuncAttributeMaxDynamicSharedMemorySize, GEMM_SMEM);
    cudaFuncSetAttribute(gemm_h, cudaFuncAttributeMaxDynamicSharedMemorySize, GEMM_SMEM);

    norms4_kernel<<<dim3(114, 2, 4), 256>>>(fq4, fs4, C4, 0);
    norms4_kernel<<<dim3(114, 2, 4), 256>>>(fq3, fs3, C3, 2);

    transpose_kernel<<<dim3(113, C4 / 64, NB * 2), 256>>>(fq4, fs4, C4, 0,  0);
    transpose_kernel<<<dim3(113, C3 / 64, NB * 2), 256>>>(fq3, fs3, C3, C4, 2);

    vprep_kernel<<<(NB * CQ * KP / 2 + 255) / 256, 256>>>(f_s);

    // corr GEMM with fused exp(10*logit) epilogue -> attnH (half) + psum
    corr_gemm<<<dim3(NTB, NTB, NB), 256, GEMM_SMEM>>>(
        (const __half*)pAh, (const __half*)pBh, (__half*)pAttnH, (float*)pPsum);

    sumred_kernel<<<(NB * HW + 255) / 256, 256>>>();

    // attn GEMM with split-K=2: partials into g_attP (reduced inside combine)
    gemm_h<<<dim3(29, 2, NB * 2), 256, GEMM_SMEM>>>(
        (const __half*)pVh, (const __half*)pAttnH, (float*)pAttP,
        KP, KP / 64, CQ, HW,
        (size_t)CQ * KP, (size_t)HW * KP, (size_t)CQ * HW, 2);

    int writeAtt = (out_size >= 2 * SZQ) ? 1 : 0;
    combine_kernel<<<113, 256>>>(f_q, out, out + SZQ, writeAtt);
}

// round 15
// speedup vs baseline: 1.2069x; 1.0061x over previous
#include <cuda_runtime.h>
#include <cuda_fp16.h>
#include <cstdint>
#include <math.h>

#define HW     3600
#define NB     2
#define CK     3072      // 2048 + 1024 stacked channels
#define C4     2048
#define C3     1024
#define CQ     256
#define KP     3648      // HW padded for attn GEMM K dim
#define NTB    29        // n-tile blocks in corr GEMM (29*128 >= 3600)
#define ATT_WT 0.5f
#define EPS    1e-12f

#define SZ3    (NB * C3 * HW)
#define SZ4    (NB * C4 * HW)
#define SZQ    (NB * CQ * HW)

// ---------------- scratch ----------------------------------------------------
__device__ __half g_Ah[(size_t)NB * HW * CK];     // norm q feats half K-major [b][m][k]
__device__ __half g_Bh[(size_t)NB * HW * CK];     // norm s feats half K-major [b][n][k]
__device__ __half g_attnH[(size_t)NB * HW * KP];  // UNNORMALIZED exp(logits) [b][q][s pad]
__device__ __half g_Vh[(size_t)NB * CQ * KP];     // f_s half                 [b][c][s pad]
__device__ float  g_psum[(size_t)NB * NTB * HW];  // per-nblock row sums      [b][nblk][q]
__device__ float  g_attP[(size_t)NB * 2 * CQ * HW]; // split-K partials       [b*2+k][c][q]
__device__ float  g_nrm[16 * NB * HW];            // partial sumsq [sel4][quarter4][b][p]

__device__ __forceinline__ uint32_t smem_u32(const void* p) {
    uint32_t a;
    asm("{ .reg .u64 t; cvta.to.shared.u64 t, %1; cvt.u32.u64 %0, t; }" : "=r"(a) : "l"(p));
    return a;
}
__device__ __forceinline__ void mma_f16(float* d, const uint32_t* a, const uint32_t* b) {
    asm volatile(
        "mma.sync.aligned.m16n8k16.row.col.f32.f16.f16.f32 "
        "{%0,%1,%2,%3}, {%4,%5,%6,%7}, {%8,%9}, {%0,%1,%2,%3};"
        : "+f"(d[0]), "+f"(d[1]), "+f"(d[2]), "+f"(d[3])
        : "r"(a[0]), "r"(a[1]), "r"(a[2]), "r"(a[3]), "r"(b[0]), "r"(b[1]));
}

// ---------------- 1a) partial sum-of-squares, single launch -------------------
// grid: (114, 2, 8); z = quarter + 4*scaleIdx (0:C4, 1:C3)
__global__ void norms4_kernel(const float* __restrict__ q4, const float* __restrict__ s4,
                              const float* __restrict__ q3, const float* __restrict__ s3) {
    int which = blockIdx.y;               // 0 = q tensor, 1 = s tensor
    int zi    = blockIdx.z;
    int scale = zi >> 2;                  // 0 = C4 pair, 1 = C3 pair
    int cq    = zi & 3;                   // channel quarter
    const float* in = scale ? (which ? s3 : q3) : (which ? s4 : q4);
    int Cf  = scale ? C3 : C4;
    int sel = scale * 2 + which;
    int b   = blockIdx.x / 57;
    int p0  = (blockIdx.x % 57) * 64;
    int Cq  = Cf >> 2;
    int tid = threadIdx.x;
    int px4 = tid & 15;
    int cg  = tid >> 4;
    bool pv = (p0 + 4 * px4 + 3 < HW);

    float4 a = make_float4(0.f, 0.f, 0.f, 0.f);
    if (pv) {
        const float* base = in + ((size_t)b * Cf + (size_t)cq * Cq) * HW + p0 + 4 * px4;
        #pragma unroll 4
        for (int c = cg; c < Cq; c += 16) {
            float4 x = *(const float4*)(base + (size_t)c * HW);
            a.x += x.x * x.x; a.y += x.y * x.y; a.z += x.z * x.z; a.w += x.w * x.w;
        }
    }
    __shared__ float part[16][64];
    part[cg][4 * px4 + 0] = a.x;
    part[cg][4 * px4 + 1] = a.y;
    part[cg][4 * px4 + 2] = a.z;
    part[cg][4 * px4 + 3] = a.w;
    __syncthreads();
    if (tid < 64 && p0 + tid < HW) {
        float t = 0.f;
        #pragma unroll
        for (int g = 0; g < 16; g++) t += part[g][tid];
        g_nrm[(((size_t)sel * 4 + cq) * NB + b) * HW + p0 + tid] = t;
    }
}

// ---------------- 1b) scale + transpose + half, single launch -----------------
// grid: (113, 48, 4); y<32 -> C4 segment, else C3; z = b*2 + which
__global__ void transpose_kernel(const float* __restrict__ q4, const float* __restrict__ s4,
                                 const float* __restrict__ q3, const float* __restrict__ s3) {
    __shared__ __half sh[32][66];
    int z  = blockIdx.z;
    int b  = z >> 1;
    int which = z & 1;                     // 0 = q (->g_Ah), 1 = s (->g_Bh)
    int yy = blockIdx.y;
    int scale = (yy >= 32);                // 0 = C4, 1 = C3
    const float* in = scale ? (which ? s3 : q3) : (which ? s4 : q4);
    int Cf   = scale ? C3 : C4;
    int c0   = (scale ? (yy - 32) : yy) * 64;
    int coff = scale ? C4 : 0;
    int nsel = scale * 2 + which;
    int p0 = blockIdx.x * 32;
    int tid = threadIdx.x;
    int tx = tid & 31, ty = tid >> 5;       // ty 0..7

    int p = p0 + tx;
    bool pv = (p < HW);
    float inv = 0.f;
    if (pv) {
        size_t nb = ((size_t)nsel * 4 * NB + b) * HW + p;
        float s = g_nrm[nb] + g_nrm[nb + (size_t)NB * HW]
                + g_nrm[nb + (size_t)2 * NB * HW] + g_nrm[nb + (size_t)3 * NB * HW];
        inv = 1.f / fmaxf(sqrtf(s), EPS);
    }
    const float* X = in + ((size_t)b * Cf + c0) * HW + p;
    #pragma unroll
    for (int j = 0; j < 8; j++) {
        int c = ty * 8 + j;
        float v = pv ? X[(size_t)c * HW] : 0.f;
        sh[tx][c] = __float2half_rn(v * inv);
    }
    __syncthreads();
    __half* T = (which ? g_Bh : g_Ah) + (size_t)b * HW * CK + coff + c0;
    #pragma unroll
    for (int k = 0; k < 4; k++) {
        int e  = tid + k * 256;
        int pr = e >> 5;
        int ln = e & 31;
        if (p0 + pr < HW) {
            uint32_t w = *(const uint32_t*)&sh[pr][2 * ln];
            *(uint32_t*)&T[(size_t)(p0 + pr) * CK + 2 * ln] = w;
        }
    }
}

// ---------------- 2a) corr GEMM + fused exp + partial row sums ---------------
// attnH[q][s] = exp(10 * cos);  logits in [-10,10] -> exp safe, no max needed.
#define SROW_H  72
#define ROW_B   144
#define STG_B   (256 * ROW_B)              // 36864 B
#define GEMM_SMEM (2 * STG_B)              // 73728 B -> 2 CTAs/SM

__global__ __launch_bounds__(256, 2)
void corr_gemm(const __half* __restrict__ Aall, const __half* __restrict__ Ball,
               __half* __restrict__ Eall, float* __restrict__ psum) {
    extern __shared__ __align__(16) char smh[];
    __shared__ float rs[128];
    uint32_t sbase = smem_u32(smh);
    int tid = threadIdx.x;
    int wid = tid >> 5, lane = tid & 31;
    int grp = lane >> 2, tig = lane & 3;
    int wm = (wid & 3) * 32;
    int wn = (wid >> 2) * 64;
    int b  = blockIdx.z;
    int m0 = blockIdx.y * 128;
    int n0 = blockIdx.x * 128;
    const __half* A = Aall + (size_t)b * HW * CK;
    const __half* B = Ball + (size_t)b * HW * CK;

    float acc[2][8][4];
    #pragma unroll
    for (int mi = 0; mi < 2; mi++)
        #pragma unroll
        for (int ni = 0; ni < 8; ni++)
            #pragma unroll
            for (int j = 0; j < 4; j++) acc[mi][ni][j] = 0.f;

    auto load_tile = [&](int iter, int s) {
        int k0 = iter * 64;
        uint32_t stA = sbase + s * STG_B;
        #pragma unroll
        for (int j = 0; j < 4; j++) {
            int f = tid + j * 256;
            int row = f >> 3, q = f & 7;
            uint32_t nb = (m0 + row < HW) ? 16u : 0u;
            const __half* gp = A + (size_t)(nb ? m0 + row : 0) * CK + k0 + q * 8;
            uint32_t sa = stA + row * ROW_B + q * 16;
            asm volatile("cp.async.cg.shared.global [%0], [%1], 16, %2;"
                         :: "r"(sa), "l"(gp), "r"(nb) : "memory");
        }
        #pragma unroll
        for (int j = 0; j < 4; j++) {
            int f = tid + j * 256;
            int row = f >> 3, q = f & 7;
            uint32_t nb = (n0 + row < HW) ? 16u : 0u;
            const __half* gp = B + (size_t)(nb ? n0 + row : 0) * CK + k0 + q * 8;
            uint32_t sa = stA + 128 * ROW_B + row * ROW_B + q * 16;
            asm volatile("cp.async.cg.shared.global [%0], [%1], 16, %2;"
                         :: "r"(sa), "l"(gp), "r"(nb) : "memory");
        }
        asm volatile("cp.async.commit_group;" ::: "memory");
    };

    const int NIT = CK / 64;   // 48
    load_tile(0, 0);
    load_tile(1, 1);

    for (int i = 0; i < NIT; i++) {
        int s = i & 1;
        if (i + 1 < NIT) { asm volatile("cp.async.wait_group 1;" ::: "memory"); }
        else            { asm volatile("cp.async.wait_group 0;" ::: "memory"); }
        __syncthreads();

        const __half* as = (const __half*)(smh + (size_t)s * STG_B);
        const __half* bs = as + 128 * SROW_H;
        #pragma unroll
        for (int ks = 0; ks < 4; ks++) {
            int kk = ks * 16;
            uint32_t af[2][4];
            #pragma unroll
            for (int mi = 0; mi < 2; mi++) {
                int r = wm + mi * 16 + grp;
                af[mi][0] = *(const uint32_t*)&as[r * SROW_H + kk + 2 * tig];
                af[mi][1] = *(const uint32_t*)&as[(r + 8) * SROW_H + kk + 2 * tig];
                af[mi][2] = *(const uint32_t*)&as[r * SROW_H + kk + 8 + 2 * tig];
                af[mi][3] = *(const uint32_t*)&as[(r + 8) * SROW_H + kk + 8 + 2 * tig];
            }
            uint32_t bf[8][2];
            #pragma unroll
            for (int ni = 0; ni < 8; ni++) {
                int r = wn + ni * 8 + grp;
                bf[ni][0] = *(const uint32_t*)&bs[r * SROW_H + kk + 2 * tig];
                bf[ni][1] = *(const uint32_t*)&bs[r * SROW_H + kk + 8 + 2 * tig];
            }
            #pragma unroll
            for (int mi = 0; mi < 2; mi++)
                #pragma unroll
                for (int ni = 0; ni < 8; ni++)
                    mma_f16(acc[mi][ni], af[mi], bf[ni]);
        }
        __syncthreads();
        if (i + 2 < NIT) load_tile(i + 2, s);
    }

    // ---- fused fast-exp epilogue + deterministic row-sum partials ------------
    float rsum[2][2] = {{0.f, 0.f}, {0.f, 0.f}};
    #pragma unroll
    for (int mi = 0; mi < 2; mi++) {
        int r = m0 + wm + mi * 16 + grp;
        #pragma unroll
        for (int ni = 0; ni < 8; ni++) {
            int n = n0 + wn + ni * 8 + 2 * tig;
            bool nv = (n < HW);
            float e0 = nv ? __expf(10.f * acc[mi][ni][0]) : 0.f;
            float e1 = nv ? __expf(10.f * acc[mi][ni][1]) : 0.f;
            float e2 = nv ? __expf(10.f * acc[mi][ni][2]) : 0.f;
            float e3 = nv ? __expf(10.f * acc[mi][ni][3]) : 0.f;
            rsum[mi][0] += e0 + e1;
            rsum[mi][1] += e2 + e3;
            if (nv) {
                if (r < HW)
                    *(__half2*)&Eall[((size_t)b * HW + r) * KP + n] = __floats2half2_rn(e0, e1);
                if (r + 8 < HW)
                    *(__half2*)&Eall[((size_t)b * HW + r + 8) * KP + n] = __floats2half2_rn(e2, e3);
            }
        }
    }
    #pragma unroll
    for (int mi = 0; mi < 2; mi++)
        #pragma unroll
        for (int h = 0; h < 2; h++) {
            rsum[mi][h] += __shfl_xor_sync(0xffffffffu, rsum[mi][h], 1);
            rsum[mi][h] += __shfl_xor_sync(0xffffffffu, rsum[mi][h], 2);
        }
    __syncthreads();
    if (tig == 0 && wid < 4) {
        #pragma unroll
        for (int mi = 0; mi < 2; mi++)
            #pragma unroll
            for (int h = 0; h < 2; h++)
                rs[wm + mi * 16 + grp + h * 8] = rsum[mi][h];
    }
    __syncthreads();
    if (tig == 0 && wid >= 4) {
        #pragma unroll
        for (int mi = 0; mi < 2; mi++)
            #pragma unroll
            for (int h = 0; h < 2; h++)
                rs[wm + mi * 16 + grp + h * 8] += rsum[mi][h];
    }
    __syncthreads();
    if (tid < 128) {
        int m = m0 + tid;
        if (m < HW)
            psum[((size_t)b * NTB + blockIdx.x) * HW + m] = rs[tid];
    }
}

// ---------------- 2b) attn GEMM: 128x128, split-K ----------------------------
__global__ __launch_bounds__(256, 2)
void gemm_h(const __half* __restrict__ Aall, const __half* __restrict__ Ball,
            float* __restrict__ Call, int ldk, int nIter, int Mg, int Ng,
            size_t strideA, size_t strideB, size_t strideC, int nSplit) {
    extern __shared__ __align__(16) char smh[];
    uint32_t sbase = smem_u32(smh);
    int tid = threadIdx.x;
    int wid = tid >> 5, lane = tid & 31;
    int grp = lane >> 2, tig = lane & 3;
    int wm = (wid & 3) * 32;
    int wn = (wid >> 2) * 64;
    int z   = blockIdx.z;
    int b   = z / nSplit;
    int ksp = z - b * nSplit;
    int m0 = blockIdx.y * 128;
    int n0 = blockIdx.x * 128;
    const __half* A = Aall + (size_t)b * strideA;
    const __half* B = Ball + (size_t)b * strideB;
    float* Cb = Call + (size_t)z * strideC;

    int per = (nIter + nSplit - 1) / nSplit;
    int i0  = ksp * per;
    int i1  = min(nIter, i0 + per);

    float acc[2][8][4];
    #pragma unroll
    for (int mi = 0; mi < 2; mi++)
        #pragma unroll
        for (int ni = 0; ni < 8; ni++)
            #pragma unroll
            for (int j = 0; j < 4; j++) acc[mi][ni][j] = 0.f;

    auto load_tile = [&](int iter, int s) {
        int k0 = iter * 64;
        uint32_t stA = sbase + s * STG_B;
        #pragma unroll
        for (int j = 0; j < 4; j++) {
            int f = tid + j * 256;
            int row = f >> 3, q = f & 7;
            uint32_t nb = (m0 + row < Mg) ? 16u : 0u;
            const __half* gp = A + (size_t)(nb ? m0 + row : 0) * ldk + k0 + q * 8;
            uint32_t sa = stA + row * ROW_B + q * 16;
            asm volatile("cp.async.cg.shared.global [%0], [%1], 16, %2;"
                         :: "r"(sa), "l"(gp), "r"(nb) : "memory");
        }
        #pragma unroll
        for (int j = 0; j < 4; j++) {
            int f = tid + j * 256;
            int row = f >> 3, q = f & 7;
            uint32_t nb = (n0 + row < Ng) ? 16u : 0u;
            const __half* gp = B + (size_t)(nb ? n0 + row : 0) * ldk + k0 + q * 8;
            uint32_t sa = stA + 128 * ROW_B + row * ROW_B + q * 16;
            asm volatile("cp.async.cg.shared.global [%0], [%1], 16, %2;"
                         :: "r"(sa), "l"(gp), "r"(nb) : "memory");
        }
        asm volatile("cp.async.commit_group;" ::: "memory");
    };

    load_tile(i0, 0);
    if (i0 + 1 < i1) load_tile(i0 + 1, 1);

    for (int i = i0; i < i1; i++) {
        int s = (i - i0) & 1;
        if (i + 1 < i1) { asm volatile("cp.async.wait_group 1;" ::: "memory"); }
        else           { asm volatile("cp.async.wait_group 0;" ::: "memory"); }
        __syncthreads();

        const __half* as = (const __half*)(smh + (size_t)s * STG_B);
        const __half* bs = as + 128 * SROW_H;
        #pragma unroll
        for (int ks = 0; ks < 4; ks++) {
            int kk = ks * 16;
            uint32_t af[2][4];
            #pragma unroll
            for (int mi = 0; mi < 2; mi++) {
                int r = wm + mi * 16 + grp;
                af[mi][0] = *(const uint32_t*)&as[r * SROW_H + kk + 2 * tig];
                af[mi][1] = *(const uint32_t*)&as[(r + 8) * SROW_H + kk + 2 * tig];
                af[mi][2] = *(const uint32_t*)&as[r * SROW_H + kk + 8 + 2 * tig];
                af[mi][3] = *(const uint32_t*)&as[(r + 8) * SROW_H + kk + 8 + 2 * tig];
            }
            uint32_t bf[8][2];
            #pragma unroll
            for (int ni = 0; ni < 8; ni++) {
                int r = wn + ni * 8 + grp;
                bf[ni][0] = *(const uint32_t*)&bs[r * SROW_H + kk + 2 * tig];
                bf[ni][1] = *(const uint32_t*)&bs[r * SROW_H + kk + 8 + 2 * tig];
            }
            #pragma unroll
            for (int mi = 0; mi < 2; mi++)
                #pragma unroll
                for (int ni = 0; ni < 8; ni++)
                    mma_f16(acc[mi][ni], af[mi], bf[ni]);
        }
        __syncthreads();
        if (i + 2 < i1) load_tile(i + 2, s);
    }

    #pragma unroll
    for (int mi = 0; mi < 2; mi++) {
        int mrow = m0 + wm + mi * 16 + grp;
        #pragma unroll
        for (int ni = 0; ni < 8; ni++) {
            int n = n0 + wn + ni * 8 + 2 * tig;
            if (n < Ng) {
                if (mrow < Mg)
                    *(float2*)&Cb[(size_t)mrow * HW + n] =
                        make_float2(acc[mi][ni][0], acc[mi][ni][1]);
                if (mrow + 8 < Mg)
                    *(float2*)&Cb[(size_t)(mrow + 8) * HW + n] =
                        make_float2(acc[mi][ni][2], acc[mi][ni][3]);
            }
        }
    }
}

// ---------------- 3) f_s -> half, K-padded, vectorized ------------------------
__global__ void vprep_kernel(const float* __restrict__ V) {
    int idx = blockIdx.x * blockDim.x + threadIdx.x;
    if (idx >= NB * CQ * KP / 2) return;
    int s2 = idx % (KP / 2);
    int bc = idx / (KP / 2);
    int s  = 2 * s2;
    __half2 h;
    if (s + 1 < HW) {
        float2 v = *(const float2*)&V[(size_t)bc * HW + s];
        h = __floats2half2_rn(v.x, v.y);
    } else {
        h = __floats2half2_rn(0.f, 0.f);
    }
    *(__half2*)&g_Vh[(size_t)bc * KP + s] = h;
}

// ---------------- 4) combine: split-K + denom reduce + outputs ----------------
// block: 4 channel-groups x 64 pixels; grid: 113
__global__ void combine_kernel(const float* __restrict__ f_q,
                               float* __restrict__ out_fq,
                               float* __restrict__ out_att, int writeAtt) {
    int tid = threadIdx.x;
    int cg  = tid >> 6;                    // 0..3
    int pl  = tid & 63;
    int gpix = blockIdx.x * 64 + pl;       // 0 .. NB*HW-1
    bool pv = (gpix < NB * HW);
    int b = pv ? gpix / HW : 0;
    int p = pv ? gpix % HW : 0;

    const float* qb = f_q + (size_t)b * CQ * HW + p;
    const float* a0 = g_attP + ((size_t)2 * b) * CQ * HW + p;
    const float* a1 = g_attP + ((size_t)2 * b + 1) * CQ * HW + p;

    float sq = 0.f, sa = 0.f;
    if (pv) {
        #pragma unroll 8
        for (int c = cg * 64; c < cg * 64 + 64; c++) {
            float x = qb[(size_t)c * HW]; sq += x * x;
            float y = a0[(size_t)c * HW] + a1[(size_t)c * HW]; sa += y * y;
        }
    }
    // fused softmax-denominator reduce (8 psum terms per channel-group)
    float ds = 0.f;
    if (pv) {
        #pragma unroll
        for (int t = cg; t < NTB; t += 4)
            ds += g_psum[((size_t)b * NTB + t) * HW + p];
    }
    __shared__ float sQ[4][64], sA[4][64], sD[4][64];
    sQ[cg][pl] = sq;
    sA[cg][pl] = sa;
    sD[cg][pl] = ds;
    __syncthreads();
    float tq = sQ[0][pl] + sQ[1][pl] + sQ[2][pl] + sQ[3][pl];
    float ta = sA[0][pl] + sA[1][pl] + sA[2][pl] + sA[3][pl];
    float td = sD[0][pl] + sD[1][pl] + sD[2][pl] + sD[3][pl];
    float iq = 1.f / fmaxf(sqrtf(tq), EPS);
    float ia = ATT_WT / fmaxf(sqrtf(ta), EPS);   // scale of y cancels in l2norm
    float rsden = 1.f / td;

    if (pv) {
        float* ob = out_fq + (size_t)b * CQ * HW + p;
        if (writeAtt) {
            float* oa = out_att + (size_t)b * CQ * HW + p;
            #pragma unroll 4
            for (int c = cg * 64; c < cg * 64 + 64; c++) {
                float y = a0[(size_t)c * HW] + a1[(size_t)c * HW];
                ob[(size_t)c * HW] = qb[(size_t)c * HW] * iq + y * ia;
                oa[(size_t)c * HW] = y * rsden;
            }
        } else {
            #pragma unroll 4
            for (int c = cg * 64; c < cg * 64 + 64; c++) {
                float y = a0[(size_t)c * HW] + a1[(size_t)c * HW];
                ob[(size_t)c * HW] = qb[(size_t)c * HW] * iq + y * ia;
            }
        }
    }
}

// ---------------- launch ------------------------------------------------------
extern "C" void kernel_launch(void* const* d_in, const int* in_sizes, int n_in,
                              void* d_out, int out_size) {
    const float *fq3 = 0, *fs3 = 0, *fq4 = 0, *fs4 = 0, *f_q = 0, *f_s = 0;
    for (int i = 0; i < n_in; i++) {
        const float* p = (const float*)d_in[i];
        int sz = in_sizes[i];
        if (sz == SZ3)      { if (!fq3) fq3 = p; else fs3 = p; }
        else if (sz == SZ4) { if (!fq4) fq4 = p; else fs4 = p; }
        else if (sz == SZQ) { if (!f_q) f_q = p; else f_s = p; }
    }
    float* out = (float*)d_out;

    // TRUE device addresses (host shadow symbols are ATS-dereferenceable on
    // GB300 -> silent zero-data bug if passed directly).
    void *pAh, *pBh, *pAttnH, *pVh, *pAttP, *pPsum;
    cudaGetSymbolAddress(&pAh, g_Ah);
    cudaGetSymbolAddress(&pBh, g_Bh);
    cudaGetSymbolAddress(&pAttnH, g_attnH);
    cudaGetSymbolAddress(&pVh, g_Vh);
    cudaGetSymbolAddress(&pAttP, g_attP);
    cudaGetSymbolAddress(&pPsum, g_psum);

    cudaFuncSetAttribute(corr_gemm, cudaFuncAttributeMaxDynamicSharedMemorySize, GEMM_SMEM);
    cudaFuncSetAttribute(gemm_h, cudaFuncAttributeMaxDynamicSharedMemorySize, GEMM_SMEM);

    norms4_kernel<<<dim3(114, 2, 8), 256>>>(fq4, fs4, fq3, fs3);

    transpose_kernel<<<dim3(113, 48, NB * 2), 256>>>(fq4, fs4, fq3, fs3);

    vprep_kernel<<<(NB * CQ * KP / 2 + 255) / 256, 256>>>(f_s);

    // corr GEMM with fused exp(10*logit) epilogue -> attnH (half) + psum
    corr_gemm<<<dim3(NTB, NTB, NB), 256, GEMM_SMEM>>>(
        (const __half*)pAh, (const __half*)pBh, (__half*)pAttnH, (float*)pPsum);

    // attn GEMM with split-K=2: partials into g_attP (reduced inside combine)
    gemm_h<<<dim3(29, 2, NB * 2), 256, GEMM_SMEM>>>(
        (const __half*)pVh, (const __half*)pAttnH, (float*)pAttP,
        KP, KP / 64, CQ, HW,
        (size_t)CQ * KP, (size_t)HW * KP, (size_t)CQ * HW, 2);

    int writeAtt = (out_size >= 2 * SZQ) ? 1 : 0;
    combine_kernel<<<113, 256>>>(f_q, out, out + SZQ, writeAtt);
}

// round 16
// speedup vs baseline: 1.4297x; 1.1846x over previous
#include <cuda_runtime.h>
#include <cuda_fp16.h>
#include <cstdint>
#include <math.h>

#define HW     3600
#define NB     2
#define CK     3072      // 2048 + 1024 stacked channels
#define C4     2048
#define C3     1024
#define CQ     256
#define KP     3648      // HW padded for attn GEMM K dim
#define NTB    29        // n-tile blocks in corr GEMM (29*128 >= 3600)
#define ATT_WT 0.5f
#define EPS    1e-12f

#define SZ3    (NB * C3 * HW)
#define SZ4    (NB * C4 * HW)
#define SZQ    (NB * CQ * HW)

// ---------------- scratch ----------------------------------------------------
__device__ __half g_Ah[(size_t)NB * HW * CK];     // norm q feats half K-major [b][m][k]
__device__ __half g_Bh[(size_t)NB * HW * CK];     // norm s feats half K-major [b][n][k]
__device__ __half g_attnH[(size_t)NB * HW * KP];  // UNNORMALIZED exp(logits) [b][q][s pad]
__device__ __half g_Vh[(size_t)NB * CQ * KP];     // f_s half                 [b][c][s pad]
__device__ float  g_psum[(size_t)NB * NTB * HW];  // per-nblock row sums      [b][nblk][q]
__device__ float  g_attP[(size_t)NB * 2 * CQ * HW]; // split-K partials       [b*2+k][c][q]
__device__ float  g_nrm[16 * NB * HW];            // partial sumsq [sel4][quarter4][b][p]

__device__ __forceinline__ uint32_t smem_u32(const void* p) {
    uint32_t a;
    asm("{ .reg .u64 t; cvta.to.shared.u64 t, %1; cvt.u32.u64 %0, t; }" : "=r"(a) : "l"(p));
    return a;
}
__device__ __forceinline__ void mma_f16(float* d, const uint32_t* a, const uint32_t* b) {
    asm volatile(
        "mma.sync.aligned.m16n8k16.row.col.f32.f16.f16.f32 "
        "{%0,%1,%2,%3}, {%4,%5,%6,%7}, {%8,%9}, {%0,%1,%2,%3};"
        : "+f"(d[0]), "+f"(d[1]), "+f"(d[2]), "+f"(d[3])
        : "r"(a[0]), "r"(a[1]), "r"(a[2]), "r"(a[3]), "r"(b[0]), "r"(b[1]));
}
__device__ __forceinline__ void ldsm4(uint32_t& r0, uint32_t& r1, uint32_t& r2,
                                      uint32_t& r3, uint32_t a) {
    asm volatile("ldmatrix.sync.aligned.m8n8.x4.shared.b16 {%0,%1,%2,%3}, [%4];"
                 : "=r"(r0), "=r"(r1), "=r"(r2), "=r"(r3) : "r"(a));
}

// ---------------- 1a) partial sum-of-squares, single launch -------------------
__global__ void norms4_kernel(const float* __restrict__ q4, const float* __restrict__ s4,
                              const float* __restrict__ q3, const float* __restrict__ s3) {
    int which = blockIdx.y;
    int zi    = blockIdx.z;
    int scale = zi >> 2;
    int cq    = zi & 3;
    const float* in = scale ? (which ? s3 : q3) : (which ? s4 : q4);
    int Cf  = scale ? C3 : C4;
    int sel = scale * 2 + which;
    int b   = blockIdx.x / 57;
    int p0  = (blockIdx.x % 57) * 64;
    int Cq  = Cf >> 2;
    int tid = threadIdx.x;
    int px4 = tid & 15;
    int cg  = tid >> 4;
    bool pv = (p0 + 4 * px4 + 3 < HW);

    float4 a = make_float4(0.f, 0.f, 0.f, 0.f);
    if (pv) {
        const float* base = in + ((size_t)b * Cf + (size_t)cq * Cq) * HW + p0 + 4 * px4;
        #pragma unroll 4
        for (int c = cg; c < Cq; c += 16) {
            float4 x = *(const float4*)(base + (size_t)c * HW);
            a.x += x.x * x.x; a.y += x.y * x.y; a.z += x.z * x.z; a.w += x.w * x.w;
        }
    }
    __shared__ float part[16][64];
    part[cg][4 * px4 + 0] = a.x;
    part[cg][4 * px4 + 1] = a.y;
    part[cg][4 * px4 + 2] = a.z;
    part[cg][4 * px4 + 3] = a.w;
    __syncthreads();
    if (tid < 64 && p0 + tid < HW) {
        float t = 0.f;
        #pragma unroll
        for (int g = 0; g < 16; g++) t += part[g][tid];
        g_nrm[(((size_t)sel * 4 + cq) * NB + b) * HW + p0 + tid] = t;
    }
}

// ---------------- 1b) scale + transpose + half, single launch -----------------
__global__ void transpose_kernel(const float* __restrict__ q4, const float* __restrict__ s4,
                                 const float* __restrict__ q3, const float* __restrict__ s3) {
    __shared__ __half sh[32][66];
    int z  = blockIdx.z;
    int b  = z >> 1;
    int which = z & 1;
    int yy = blockIdx.y;
    int scale = (yy >= 32);
    const float* in = scale ? (which ? s3 : q3) : (which ? s4 : q4);
    int Cf   = scale ? C3 : C4;
    int c0   = (scale ? (yy - 32) : yy) * 64;
    int coff = scale ? C4 : 0;
    int nsel = scale * 2 + which;
    int p0 = blockIdx.x * 32;
    int tid = threadIdx.x;
    int tx = tid & 31, ty = tid >> 5;

    int p = p0 + tx;
    bool pv = (p < HW);
    float inv = 0.f;
    if (pv) {
        size_t nb = ((size_t)nsel * 4 * NB + b) * HW + p;
        float s = g_nrm[nb] + g_nrm[nb + (size_t)NB * HW]
                + g_nrm[nb + (size_t)2 * NB * HW] + g_nrm[nb + (size_t)3 * NB * HW];
        inv = 1.f / fmaxf(sqrtf(s), EPS);
    }
    const float* X = in + ((size_t)b * Cf + c0) * HW + p;
    #pragma unroll
    for (int j = 0; j < 8; j++) {
        int c = ty * 8 + j;
        float v = pv ? X[(size_t)c * HW] : 0.f;
        sh[tx][c] = __float2half_rn(v * inv);
    }
    __syncthreads();
    __half* T = (which ? g_Bh : g_Ah) + (size_t)b * HW * CK + coff + c0;
    #pragma unroll
    for (int k = 0; k < 4; k++) {
        int e  = tid + k * 256;
        int pr = e >> 5;
        int ln = e & 31;
        if (p0 + pr < HW) {
            uint32_t w = *(const uint32_t*)&sh[pr][2 * ln];
            *(uint32_t*)&T[(size_t)(p0 + pr) * CK + 2 * ln] = w;
        }
    }
}

// ---------------- GEMM smem: 128B rows, XOR swizzle, ldmatrix fragments ------
#define STG_B   32768                      // (128+128 rows) * 128 B per stage
#define GEMM_SMEM (2 * STG_B)              // 65536 B -> 2 CTAs/SM

// ---------------- 2a) corr GEMM + fused exp + partial row sums ---------------
__global__ __launch_bounds__(256, 2)
void corr_gemm(const __half* __restrict__ Aall, const __half* __restrict__ Ball,
               __half* __restrict__ Eall, float* __restrict__ psum) {
    extern __shared__ __align__(16) char smh[];
    __shared__ float rs[128];
    uint32_t sbase = smem_u32(smh);
    int tid = threadIdx.x;
    int wid = tid >> 5, lane = tid & 31;
    int grp = lane >> 2, tig = lane & 3;
    int wm = (wid & 3) * 32;
    int wn = (wid >> 2) * 64;
    int b  = blockIdx.z;
    int m0 = blockIdx.y * 128;
    int n0 = blockIdx.x * 128;
    const __half* A = Aall + (size_t)b * HW * CK;
    const __half* B = Ball + (size_t)b * HW * CK;

    float acc[2][8][4];
    #pragma unroll
    for (int mi = 0; mi < 2; mi++)
        #pragma unroll
        for (int ni = 0; ni < 8; ni++)
            #pragma unroll
            for (int j = 0; j < 4; j++) acc[mi][ni][j] = 0.f;

    // ldmatrix per-lane bases
    uint32_t hiA = lane >> 4;
    uint32_t aOff[2], aR7[2];
    #pragma unroll
    for (int mi = 0; mi < 2; mi++) {
        int r = wm + mi * 16 + (lane & 15);
        aOff[mi] = r * 128;
        aR7[mi]  = r & 7;
    }
    uint32_t quad = lane >> 3;
    uint32_t hiB = quad & 1;
    uint32_t bOff[4], bR7[4];
    #pragma unroll
    for (int nt = 0; nt < 4; nt++) {
        int r = wn + nt * 16 + ((quad >> 1) << 3) + (lane & 7);
        bOff[nt] = r * 128;
        bR7[nt]  = r & 7;
    }

    auto load_tile = [&](int iter, int s) {
        int k0 = iter * 64;
        uint32_t stA = sbase + s * STG_B;
        #pragma unroll
        for (int j = 0; j < 4; j++) {
            int f = tid + j * 256;
            int row = f >> 3, q = f & 7;
            uint32_t nb = (m0 + row < HW) ? 16u : 0u;
            const __half* gp = A + (size_t)(nb ? m0 + row : 0) * CK + k0 + q * 8;
            uint32_t sa = stA + row * 128 + ((q ^ (row & 7)) << 4);
            asm volatile("cp.async.cg.shared.global [%0], [%1], 16, %2;"
                         :: "r"(sa), "l"(gp), "r"(nb) : "memory");
        }
        #pragma unroll
        for (int j = 0; j < 4; j++) {
            int f = tid + j * 256;
            int row = f >> 3, q = f & 7;
            uint32_t nb = (n0 + row < HW) ? 16u : 0u;
            const __half* gp = B + (size_t)(nb ? n0 + row : 0) * CK + k0 + q * 8;
            uint32_t sa = stA + 16384 + row * 128 + ((q ^ (row & 7)) << 4);
            asm volatile("cp.async.cg.shared.global [%0], [%1], 16, %2;"
                         :: "r"(sa), "l"(gp), "r"(nb) : "memory");
        }
        asm volatile("cp.async.commit_group;" ::: "memory");
    };

    const int NIT = CK / 64;   // 48
    load_tile(0, 0);
    load_tile(1, 1);

    for (int i = 0; i < NIT; i++) {
        int s = i & 1;
        if (i + 1 < NIT) { asm volatile("cp.async.wait_group 1;" ::: "memory"); }
        else            { asm volatile("cp.async.wait_group 0;" ::: "memory"); }
        __syncthreads();

        uint32_t stA = sbase + s * STG_B;
        uint32_t stB = stA + 16384;
        #pragma unroll
        for (int ks = 0; ks < 4; ks++) {
            uint32_t kk2 = ks * 2;
            uint32_t af[2][4];
            #pragma unroll
            for (int mi = 0; mi < 2; mi++) {
                uint32_t q = (kk2 + hiA) ^ aR7[mi];
                ldsm4(af[mi][0], af[mi][1], af[mi][2], af[mi][3],
                      stA + aOff[mi] + (q << 4));
            }
            uint32_t bf[8][2];
            #pragma unroll
            for (int nt = 0; nt < 4; nt++) {
                uint32_t q = (kk2 + hiB) ^ bR7[nt];
                uint32_t r0, r1, r2, r3;
                ldsm4(r0, r1, r2, r3, stB + bOff[nt] + (q << 4));
                bf[2 * nt][0] = r0; bf[2 * nt][1] = r1;
                bf[2 * nt + 1][0] = r2; bf[2 * nt + 1][1] = r3;
            }
            #pragma unroll
            for (int mi = 0; mi < 2; mi++)
                #pragma unroll
                for (int ni = 0; ni < 8; ni++)
                    mma_f16(acc[mi][ni], af[mi], bf[ni]);
        }
        __syncthreads();
        if (i + 2 < NIT) load_tile(i + 2, s);
    }

    // ---- fused fast-exp epilogue + deterministic row-sum partials ------------
    float rsum[2][2] = {{0.f, 0.f}, {0.f, 0.f}};
    #pragma unroll
    for (int mi = 0; mi < 2; mi++) {
        int r = m0 + wm + mi * 16 + grp;
        #pragma unroll
        for (int ni = 0; ni < 8; ni++) {
            int n = n0 + wn + ni * 8 + 2 * tig;
            bool nv = (n < HW);
            float e0 = nv ? __expf(10.f * acc[mi][ni][0]) : 0.f;
            float e1 = nv ? __expf(10.f * acc[mi][ni][1]) : 0.f;
            float e2 = nv ? __expf(10.f * acc[mi][ni][2]) : 0.f;
            float e3 = nv ? __expf(10.f * acc[mi][ni][3]) : 0.f;
            rsum[mi][0] += e0 + e1;
            rsum[mi][1] += e2 + e3;
            if (nv) {
                if (r < HW)
                    *(__half2*)&Eall[((size_t)b * HW + r) * KP + n] = __floats2half2_rn(e0, e1);
                if (r + 8 < HW)
                    *(__half2*)&Eall[((size_t)b * HW + r + 8) * KP + n] = __floats2half2_rn(e2, e3);
            }
        }
    }
    #pragma unroll
    for (int mi = 0; mi < 2; mi++)
        #pragma unroll
        for (int h = 0; h < 2; h++) {
            rsum[mi][h] += __shfl_xor_sync(0xffffffffu, rsum[mi][h], 1);
            rsum[mi][h] += __shfl_xor_sync(0xffffffffu, rsum[mi][h], 2);
        }
    __syncthreads();
    if (tig == 0 && wid < 4) {
        #pragma unroll
        for (int mi = 0; mi < 2; mi++)
            #pragma unroll
            for (int h = 0; h < 2; h++)
                rs[wm + mi * 16 + grp + h * 8] = rsum[mi][h];
    }
    __syncthreads();
    if (tig == 0 && wid >= 4) {
        #pragma unroll
        for (int mi = 0; mi < 2; mi++)
            #pragma unroll
            for (int h = 0; h < 2; h++)
                rs[wm + mi * 16 + grp + h * 8] += rsum[mi][h];
    }
    __syncthreads();
    if (tid < 128) {
        int m = m0 + tid;
        if (m < HW)
            psum[((size_t)b * NTB + blockIdx.x) * HW + m] = rs[tid];
    }
}

// ---------------- 2b) attn GEMM: 128x128, split-K, ldmatrix ------------------
__global__ __launch_bounds__(256, 2)
void gemm_h(const __half* __restrict__ Aall, const __half* __restrict__ Ball,
            float* __restrict__ Call, int ldk, int nIter, int Mg, int Ng,
            size_t strideA, size_t strideB, size_t strideC, int nSplit) {
    extern __shared__ __align__(16) char smh[];
    uint32_t sbase = smem_u32(smh);
    int tid = threadIdx.x;
    int wid = tid >> 5, lane = tid & 31;
    int grp = lane >> 2, tig = lane & 3;
    int wm = (wid & 3) * 32;
    int wn = (wid >> 2) * 64;
    int z   = blockIdx.z;
    int b   = z / nSplit;
    int ksp = z - b * nSplit;
    int m0 = blockIdx.y * 128;
    int n0 = blockIdx.x * 128;
    const __half* A = Aall + (size_t)b * strideA;
    const __half* B = Ball + (size_t)b * strideB;
    float* Cb = Call + (size_t)z * strideC;

    int per = (nIter + nSplit - 1) / nSplit;
    int i0  = ksp * per;
    int i1  = min(nIter, i0 + per);

    float acc[2][8][4];
    #pragma unroll
    for (int mi = 0; mi < 2; mi++)
        #pragma unroll
        for (int ni = 0; ni < 8; ni++)
            #pragma unroll
            for (int j = 0; j < 4; j++) acc[mi][ni][j] = 0.f;

    uint32_t hiA = lane >> 4;
    uint32_t aOff[2], aR7[2];
    #pragma unroll
    for (int mi = 0; mi < 2; mi++) {
        int r = wm + mi * 16 + (lane & 15);
        aOff[mi] = r * 128;
        aR7[mi]  = r & 7;
    }
    uint32_t quad = lane >> 3;
    uint32_t hiB = quad & 1;
    uint32_t bOff[4], bR7[4];
    #pragma unroll
    for (int nt = 0; nt < 4; nt++) {
        int r = wn + nt * 16 + ((quad >> 1) << 3) + (lane & 7);
        bOff[nt] = r * 128;
        bR7[nt]  = r & 7;
    }

    auto load_tile = [&](int iter, int s) {
        int k0 = iter * 64;
        uint32_t stA = sbase + s * STG_B;
        #pragma unroll
        for (int j = 0; j < 4; j++) {
            int f = tid + j * 256;
            int row = f >> 3, q = f & 7;
            uint32_t nb = (m0 + row < Mg) ? 16u : 0u;
            const __half* gp = A + (size_t)(nb ? m0 + row : 0) * ldk + k0 + q * 8;
            uint32_t sa = stA + row * 128 + ((q ^ (row & 7)) << 4);
            asm volatile("cp.async.cg.shared.global [%0], [%1], 16, %2;"
                         :: "r"(sa), "l"(gp), "r"(nb) : "memory");
        }
        #pragma unroll
        for (int j = 0; j < 4; j++) {
            int f = tid + j * 256;
            int row = f >> 3, q = f & 7;
            uint32_t nb = (n0 + row < Ng) ? 16u : 0u;
            const __half* gp = B + (size_t)(nb ? n0 + row : 0) * ldk + k0 + q * 8;
            uint32_t sa = stA + 16384 + row * 128 + ((q ^ (row & 7)) << 4);
            asm volatile("cp.async.cg.shared.global [%0], [%1], 16, %2;"
                         :: "r"(sa), "l"(gp), "r"(nb) : "memory");
        }
        asm volatile("cp.async.commit_group;" ::: "memory");
    };

    load_tile(i0, 0);
    if (i0 + 1 < i1) load_tile(i0 + 1, 1);

    for (int i = i0; i < i1; i++) {
        int s = (i - i0) & 1;
        if (i + 1 < i1) { asm volatile("cp.async.wait_group 1;" ::: "memory"); }
        else           { asm volatile("cp.async.wait_group 0;" ::: "memory"); }
        __syncthreads();

        uint32_t stA = sbase + s * STG_B;
        uint32_t stB = stA + 16384;
        #pragma unroll
        for (int ks = 0; ks < 4; ks++) {
            uint32_t kk2 = ks * 2;
            uint32_t af[2][4];
            #pragma unroll
            for (int mi = 0; mi < 2; mi++) {
                uint32_t q = (kk2 + hiA) ^ aR7[mi];
                ldsm4(af[mi][0], af[mi][1], af[mi][2], af[mi][3],
                      stA + aOff[mi] + (q << 4));
            }
            uint32_t bf[8][2];
            #pragma unroll
            for (int nt = 0; nt < 4; nt++) {
                uint32_t q = (kk2 + hiB) ^ bR7[nt];
                uint32_t r0, r1, r2, r3;
                ldsm4(r0, r1, r2, r3, stB + bOff[nt] + (q << 4));
                bf[2 * nt][0] = r0; bf[2 * nt][1] = r1;
                bf[2 * nt + 1][0] = r2; bf[2 * nt + 1][1] = r3;
            }
            #pragma unroll
            for (int mi = 0; mi < 2; mi++)
                #pragma unroll
                for (int ni = 0; ni < 8; ni++)
                    mma_f16(acc[mi][ni], af[mi], bf[ni]);
        }
        __syncthreads();
        if (i + 2 < i1) load_tile(i + 2, s);
    }

    #pragma unroll
    for (int mi = 0; mi < 2; mi++) {
        int mrow = m0 + wm + mi * 16 + grp;
        #pragma unroll
        for (int ni = 0; ni < 8; ni++) {
            int n = n0 + wn + ni * 8 + 2 * tig;
            if (n < Ng) {
                if (mrow < Mg)
                    *(float2*)&Cb[(size_t)mrow * HW + n] =
                        make_float2(acc[mi][ni][0], acc[mi][ni][1]);
                if (mrow + 8 < Mg)
                    *(float2*)&Cb[(size_t)(mrow + 8) * HW + n] =
                        make_float2(acc[mi][ni][2], acc[mi][ni][3]);
            }
        }
    }
}

// ---------------- 3) f_s -> half, K-padded, vectorized ------------------------
__global__ void vprep_kernel(const float* __restrict__ V) {
    int idx = blockIdx.x * blockDim.x + threadIdx.x;
    if (idx >= NB * CQ * KP / 2) return;
    int s2 = idx % (KP / 2);
    int bc = idx / (KP / 2);
    int s  = 2 * s2;
    __half2 h;
    if (s + 1 < HW) {
        float2 v = *(const float2*)&V[(size_t)bc * HW + s];
        h = __floats2half2_rn(v.x, v.y);
    } else {
        h = __floats2half2_rn(0.f, 0.f);
    }
    *(__half2*)&g_Vh[(size_t)bc * KP + s] = h;
}

// ---------------- 4) combine: split-K + denom reduce + outputs ----------------
__global__ void combine_kernel(const float* __restrict__ f_q,
                               float* __restrict__ out_fq,
                               float* __restrict__ out_att, int writeAtt) {
    int tid = threadIdx.x;
    int cg  = tid >> 6;
    int pl  = tid & 63;
    int gpix = blockIdx.x * 64 + pl;
    bool pv = (gpix < NB * HW);
    int b = pv ? gpix / HW : 0;
    int p = pv ? gpix % HW : 0;

    const float* qb = f_q + (size_t)b * CQ * HW + p;
    const float* a0 = g_attP + ((size_t)2 * b) * CQ * HW + p;
    const float* a1 = g_attP + ((size_t)2 * b + 1) * CQ * HW + p;

    float sq = 0.f, sa = 0.f;
    if (pv) {
        #pragma unroll 8
        for (int c = cg * 64; c < cg * 64 + 64; c++) {
            float x = qb[(size_t)c * HW]; sq += x * x;
            float y = a0[(size_t)c * HW] + a1[(size_t)c * HW]; sa += y * y;
        }
    }
    float ds = 0.f;
    if (pv) {
        #pragma unroll
        for (int t = cg; t < NTB; t += 4)
            ds += g_psum[((size_t)b * NTB + t) * HW + p];
    }
    __shared__ float sQ[4][64], sA[4][64], sD[4][64];
    sQ[cg][pl] = sq;
    sA[cg][pl] = sa;
    sD[cg][pl] = ds;
    __syncthreads();
    float tq = sQ[0][pl] + sQ[1][pl] + sQ[2][pl] + sQ[3][pl];
    float ta = sA[0][pl] + sA[1][pl] + sA[2][pl] + sA[3][pl];
    float td = sD[0][pl] + sD[1][pl] + sD[2][pl] + sD[3][pl];
    float iq = 1.f / fmaxf(sqrtf(tq), EPS);
    float ia = ATT_WT / fmaxf(sqrtf(ta), EPS);
    float rsden = 1.f / td;

    if (pv) {
        float* ob = out_fq + (size_t)b * CQ * HW + p;
        if (writeAtt) {
            float* oa = out_att + (size_t)b * CQ * HW + p;
            #pragma unroll 4
            for (int c = cg * 64; c < cg * 64 + 64; c++) {
                float y = a0[(size_t)c * HW] + a1[(size_t)c * HW];
                ob[(size_t)c * HW] = qb[(size_t)c * HW] * iq + y * ia;
                oa[(size_t)c * HW] = y * rsden;
            }
        } else {
            #pragma unroll 4
            for (int c = cg * 64; c < cg * 64 + 64; c++) {
                float y = a0[(size_t)c * HW] + a1[(size_t)c * HW];
                ob[(size_t)c * HW] = qb[(size_t)c * HW] * iq + y * ia;
            }
        }
    }
}

// ---------------- launch ------------------------------------------------------
extern "C" void kernel_launch(void* const* d_in, const int* in_sizes, int n_in,
                              void* d_out, int out_size) {
    const float *fq3 = 0, *fs3 = 0, *fq4 = 0, *fs4 = 0, *f_q = 0, *f_s = 0;
    for (int i = 0; i < n_in; i++) {
        const float* p = (const float*)d_in[i];
        int sz = in_sizes[i];
        if (sz == SZ3)      { if (!fq3) fq3 = p; else fs3 = p; }
        else if (sz == SZ4) { if (!fq4) fq4 = p; else fs4 = p; }
        else if (sz == SZQ) { if (!f_q) f_q = p; else f_s = p; }
    }
    float* out = (float*)d_out;

    // TRUE device addresses (host shadow symbols are ATS-dereferenceable on
    // GB300 -> silent zero-data bug if passed directly).
    void *pAh, *pBh, *pAttnH, *pVh, *pAttP, *pPsum;
    cudaGetSymbolAddress(&pAh, g_Ah);
    cudaGetSymbolAddress(&pBh, g_Bh);
    cudaGetSymbolAddress(&pAttnH, g_attnH);
    cudaGetSymbolAddress(&pVh, g_Vh);
    cudaGetSymbolAddress(&pAttP, g_attP);
    cudaGetSymbolAddress(&pPsum, g_psum);

    cudaFuncSetAttribute(corr_gemm, cudaFuncAttributeMaxDynamicSharedMemorySize, GEMM_SMEM);
    cudaFuncSetAttribute(gemm_h, cudaFuncAttributeMaxDynamicSharedMemorySize, GEMM_SMEM);

    norms4_kernel<<<dim3(114, 2, 8), 256>>>(fq4, fs4, fq3, fs3);

    transpose_kernel<<<dim3(113, 48, NB * 2), 256>>>(fq4, fs4, fq3, fs3);

    vprep_kernel<<<(NB * CQ * KP / 2 + 255) / 256, 256>>>(f_s);

    // corr GEMM with fused exp(10*logit) epilogue -> attnH (half) + psum
    corr_gemm<<<dim3(NTB, NTB, NB), 256, GEMM_SMEM>>>(
        (const __half*)pAh, (const __half*)pBh, (__half*)pAttnH, (float*)pPsum);

    // attn GEMM with split-K=2: partials into g_attP (reduced inside combine)
    gemm_h<<<dim3(29, 2, NB * 2), 256, GEMM_SMEM>>>(
        (const __half*)pVh, (const __half*)pAttnH, (float*)pAttP,
        KP, KP / 64, CQ, HW,
        (size_t)CQ * KP, (size_t)HW * KP, (size_t)CQ * HW, 2);

    int writeAtt = (out_size >= 2 * SZQ) ? 1 : 0;
    combine_kernel<<<113, 256>>>(f_q, out, out + SZQ, writeAtt);
}

// round 17
// speedup vs baseline: 1.4505x; 1.0145x over previous
#include <cuda_runtime.h>
#include <cuda_fp16.h>
#include <cstdint>
#include <math.h>

#define HW     3600
#define NB     2
#define CK     3072      // 2048 + 1024 stacked channels
#define C4     2048
#define C3     1024
#define CQ     256
#define KP     3648      // HW padded for attn GEMM K dim
#define NTB    29        // n-tile blocks in corr GEMM (29*128 >= 3600)
#define ATT_WT 0.5f
#define EPS    1e-12f

#define SZ3    (NB * C3 * HW)
#define SZ4    (NB * C4 * HW)
#define SZQ    (NB * CQ * HW)

// ---------------- scratch ----------------------------------------------------
__device__ __half g_Ah[(size_t)NB * HW * CK];     // norm q feats half K-major [b][m][k]
__device__ __half g_Bh[(size_t)NB * HW * CK];     // norm s feats half K-major [b][n][k]
__device__ __half g_attnH[(size_t)NB * HW * KP];  // UNNORMALIZED exp(logits) [b][q][s pad]
__device__ __half g_Vh[(size_t)NB * CQ * KP];     // f_s half                 [b][c][s pad]
__device__ float  g_psum[(size_t)NB * NTB * HW];  // per-nblock row sums      [b][nblk][q]
__device__ float  g_attP[(size_t)NB * 2 * CQ * HW]; // split-K partials       [b*2+k][c][q]
__device__ float  g_nrm[16 * NB * HW];            // partial sumsq [sel4][quarter4][b][p]

__device__ __forceinline__ uint32_t smem_u32(const void* p) {
    uint32_t a;
    asm("{ .reg .u64 t; cvta.to.shared.u64 t, %1; cvt.u32.u64 %0, t; }" : "=r"(a) : "l"(p));
    return a;
}
__device__ __forceinline__ void mma_f16(float* d, const uint32_t* a, const uint32_t* b) {
    asm volatile(
        "mma.sync.aligned.m16n8k16.row.col.f32.f16.f16.f32 "
        "{%0,%1,%2,%3}, {%4,%5,%6,%7}, {%8,%9}, {%0,%1,%2,%3};"
        : "+f"(d[0]), "+f"(d[1]), "+f"(d[2]), "+f"(d[3])
        : "r"(a[0]), "r"(a[1]), "r"(a[2]), "r"(a[3]), "r"(b[0]), "r"(b[1]));
}
__device__ __forceinline__ void ldsm4(uint32_t& r0, uint32_t& r1, uint32_t& r2,
                                      uint32_t& r3, uint32_t a) {
    asm volatile("ldmatrix.sync.aligned.m8n8.x4.shared.b16 {%0,%1,%2,%3}, [%4];"
                 : "=r"(r0), "=r"(r1), "=r"(r2), "=r"(r3) : "r"(a));
}

// ---------------- 1a) partial sum-of-squares, single launch -------------------
__global__ void norms4_kernel(const float* __restrict__ q4, const float* __restrict__ s4,
                              const float* __restrict__ q3, const float* __restrict__ s3) {
    int which = blockIdx.y;
    int zi    = blockIdx.z;
    int scale = zi >> 2;
    int cq    = zi & 3;
    const float* in = scale ? (which ? s3 : q3) : (which ? s4 : q4);
    int Cf  = scale ? C3 : C4;
    int sel = scale * 2 + which;
    int b   = blockIdx.x / 57;
    int p0  = (blockIdx.x % 57) * 64;
    int Cq  = Cf >> 2;
    int tid = threadIdx.x;
    int px4 = tid & 15;
    int cg  = tid >> 4;
    bool pv = (p0 + 4 * px4 + 3 < HW);

    float4 a = make_float4(0.f, 0.f, 0.f, 0.f);
    if (pv) {
        const float* base = in + ((size_t)b * Cf + (size_t)cq * Cq) * HW + p0 + 4 * px4;
        #pragma unroll 4
        for (int c = cg; c < Cq; c += 16) {
            float4 x = *(const float4*)(base + (size_t)c * HW);
            a.x += x.x * x.x; a.y += x.y * x.y; a.z += x.z * x.z; a.w += x.w * x.w;
        }
    }
    __shared__ float part[16][64];
    part[cg][4 * px4 + 0] = a.x;
    part[cg][4 * px4 + 1] = a.y;
    part[cg][4 * px4 + 2] = a.z;
    part[cg][4 * px4 + 3] = a.w;
    __syncthreads();
    if (tid < 64 && p0 + tid < HW) {
        float t = 0.f;
        #pragma unroll
        for (int g = 0; g < 16; g++) t += part[g][tid];
        g_nrm[(((size_t)sel * 4 + cq) * NB + b) * HW + p0 + tid] = t;
    }
}

// ---------------- 1b) scale + transpose + half, single launch -----------------
__global__ void transpose_kernel(const float* __restrict__ q4, const float* __restrict__ s4,
                                 const float* __restrict__ q3, const float* __restrict__ s3) {
    __shared__ __half sh[32][66];
    int z  = blockIdx.z;
    int b  = z >> 1;
    int which = z & 1;
    int yy = blockIdx.y;
    int scale = (yy >= 32);
    const float* in = scale ? (which ? s3 : q3) : (which ? s4 : q4);
    int Cf   = scale ? C3 : C4;
    int c0   = (scale ? (yy - 32) : yy) * 64;
    int coff = scale ? C4 : 0;
    int nsel = scale * 2 + which;
    int p0 = blockIdx.x * 32;
    int tid = threadIdx.x;
    int tx = tid & 31, ty = tid >> 5;

    int p = p0 + tx;
    bool pv = (p < HW);
    float inv = 0.f;
    if (pv) {
        size_t nb = ((size_t)nsel * 4 * NB + b) * HW + p;
        float s = g_nrm[nb] + g_nrm[nb + (size_t)NB * HW]
                + g_nrm[nb + (size_t)2 * NB * HW] + g_nrm[nb + (size_t)3 * NB * HW];
        inv = 1.f / fmaxf(sqrtf(s), EPS);
    }
    const float* X = in + ((size_t)b * Cf + c0) * HW + p;
    #pragma unroll
    for (int j = 0; j < 8; j++) {
        int c = ty * 8 + j;
        float v = pv ? X[(size_t)c * HW] : 0.f;
        sh[tx][c] = __float2half_rn(v * inv);
    }
    __syncthreads();
    __half* T = (which ? g_Bh : g_Ah) + (size_t)b * HW * CK + coff + c0;
    #pragma unroll
    for (int k = 0; k < 4; k++) {
        int e  = tid + k * 256;
        int pr = e >> 5;
        int ln = e & 31;
        if (p0 + pr < HW) {
            uint32_t w = *(const uint32_t*)&sh[pr][2 * ln];
            *(uint32_t*)&T[(size_t)(p0 + pr) * CK + 2 * ln] = w;
        }
    }
}

// ---------------- GEMM smem: 128B rows, XOR swizzle, ldmatrix, 3 stages ------
#define STG_B   32768                      // (128+128 rows) * 128 B per stage
#define GEMM_SMEM (3 * STG_B)              // 98304 B -> 2 CTAs/SM (192KB)

// ---------------- 2a) corr GEMM + fused exp + partial row sums ---------------
__global__ __launch_bounds__(256, 2)
void corr_gemm(const __half* __restrict__ Aall, const __half* __restrict__ Ball,
               __half* __restrict__ Eall, float* __restrict__ psum) {
    extern __shared__ __align__(16) char smh[];
    __shared__ float rs[128];
    uint32_t sbase = smem_u32(smh);
    int tid = threadIdx.x;
    int wid = tid >> 5, lane = tid & 31;
    int grp = lane >> 2, tig = lane & 3;
    int wm = (wid & 3) * 32;
    int wn = (wid >> 2) * 64;
    int b  = blockIdx.z;
    int m0 = blockIdx.y * 128;
    int n0 = blockIdx.x * 128;
    const __half* A = Aall + (size_t)b * HW * CK;
    const __half* B = Ball + (size_t)b * HW * CK;

    float acc[2][8][4];
    #pragma unroll
    for (int mi = 0; mi < 2; mi++)
        #pragma unroll
        for (int ni = 0; ni < 8; ni++)
            #pragma unroll
            for (int j = 0; j < 4; j++) acc[mi][ni][j] = 0.f;

    uint32_t hiA = lane >> 4;
    uint32_t aOff[2], aR7[2];
    #pragma unroll
    for (int mi = 0; mi < 2; mi++) {
        int r = wm + mi * 16 + (lane & 15);
        aOff[mi] = r * 128;
        aR7[mi]  = r & 7;
    }
    uint32_t quad = lane >> 3;
    uint32_t hiB = quad & 1;
    uint32_t bOff[4], bR7[4];
    #pragma unroll
    for (int nt = 0; nt < 4; nt++) {
        int r = wn + nt * 16 + ((quad >> 1) << 3) + (lane & 7);
        bOff[nt] = r * 128;
        bR7[nt]  = r & 7;
    }

    auto load_tile = [&](int iter, int s) {
        int k0 = iter * 64;
        uint32_t stA = sbase + s * STG_B;
        #pragma unroll
        for (int j = 0; j < 4; j++) {
            int f = tid + j * 256;
            int row = f >> 3, q = f & 7;
            uint32_t nb = (m0 + row < HW) ? 16u : 0u;
            const __half* gp = A + (size_t)(nb ? m0 + row : 0) * CK + k0 + q * 8;
            uint32_t sa = stA + row * 128 + ((q ^ (row & 7)) << 4);
            asm volatile("cp.async.cg.shared.global [%0], [%1], 16, %2;"
                         :: "r"(sa), "l"(gp), "r"(nb) : "memory");
        }
        #pragma unroll
        for (int j = 0; j < 4; j++) {
            int f = tid + j * 256;
            int row = f >> 3, q = f & 7;
            uint32_t nb = (n0 + row < HW) ? 16u : 0u;
            const __half* gp = B + (size_t)(nb ? n0 + row : 0) * CK + k0 + q * 8;
            uint32_t sa = stA + 16384 + row * 128 + ((q ^ (row & 7)) << 4);
            asm volatile("cp.async.cg.shared.global [%0], [%1], 16, %2;"
                         :: "r"(sa), "l"(gp), "r"(nb) : "memory");
        }
        asm volatile("cp.async.commit_group;" ::: "memory");
    };

    const int NIT = CK / 64;   // 48
    load_tile(0, 0);
    load_tile(1, 1);

    for (int i = 0; i < NIT; i++) {
        int s = i % 3;
        if (i + 1 < NIT) { asm volatile("cp.async.wait_group 1;" ::: "memory"); }
        else            { asm volatile("cp.async.wait_group 0;" ::: "memory"); }
        __syncthreads();                       // single barrier per iteration
        if (i + 2 < NIT) load_tile(i + 2, (i + 2) % 3);  // overlap with compute

        uint32_t stA = sbase + s * STG_B;
        uint32_t stB = stA + 16384;
        #pragma unroll
        for (int ks = 0; ks < 4; ks++) {
            uint32_t kk2 = ks * 2;
            uint32_t af[2][4];
            #pragma unroll
            for (int mi = 0; mi < 2; mi++) {
                uint32_t q = (kk2 + hiA) ^ aR7[mi];
                ldsm4(af[mi][0], af[mi][1], af[mi][2], af[mi][3],
                      stA + aOff[mi] + (q << 4));
            }
            uint32_t bf[8][2];
            #pragma unroll
            for (int nt = 0; nt < 4; nt++) {
                uint32_t q = (kk2 + hiB) ^ bR7[nt];
                uint32_t r0, r1, r2, r3;
                ldsm4(r0, r1, r2, r3, stB + bOff[nt] + (q << 4));
                bf[2 * nt][0] = r0; bf[2 * nt][1] = r1;
                bf[2 * nt + 1][0] = r2; bf[2 * nt + 1][1] = r3;
            }
            #pragma unroll
            for (int mi = 0; mi < 2; mi++)
                #pragma unroll
                for (int ni = 0; ni < 8; ni++)
                    mma_f16(acc[mi][ni], af[mi], bf[ni]);
        }
    }

    // ---- fused fast-exp epilogue + deterministic row-sum partials ------------
    float rsum[2][2] = {{0.f, 0.f}, {0.f, 0.f}};
    #pragma unroll
    for (int mi = 0; mi < 2; mi++) {
        int r = m0 + wm + mi * 16 + grp;
        #pragma unroll
        for (int ni = 0; ni < 8; ni++) {
            int n = n0 + wn + ni * 8 + 2 * tig;
            bool nv = (n < HW);
            float e0 = nv ? __expf(10.f * acc[mi][ni][0]) : 0.f;
            float e1 = nv ? __expf(10.f * acc[mi][ni][1]) : 0.f;
            float e2 = nv ? __expf(10.f * acc[mi][ni][2]) : 0.f;
            float e3 = nv ? __expf(10.f * acc[mi][ni][3]) : 0.f;
            rsum[mi][0] += e0 + e1;
            rsum[mi][1] += e2 + e3;
            if (nv) {
                if (r < HW)
                    *(__half2*)&Eall[((size_t)b * HW + r) * KP + n] = __floats2half2_rn(e0, e1);
                if (r + 8 < HW)
                    *(__half2*)&Eall[((size_t)b * HW + r + 8) * KP + n] = __floats2half2_rn(e2, e3);
            }
        }
    }
    #pragma unroll
    for (int mi = 0; mi < 2; mi++)
        #pragma unroll
        for (int h = 0; h < 2; h++) {
            rsum[mi][h] += __shfl_xor_sync(0xffffffffu, rsum[mi][h], 1);
            rsum[mi][h] += __shfl_xor_sync(0xffffffffu, rsum[mi][h], 2);
        }
    __syncthreads();
    if (tig == 0 && wid < 4) {
        #pragma unroll
        for (int mi = 0; mi < 2; mi++)
            #pragma unroll
            for (int h = 0; h < 2; h++)
                rs[wm + mi * 16 + grp + h * 8] = rsum[mi][h];
    }
    __syncthreads();
    if (tig == 0 && wid >= 4) {
        #pragma unroll
        for (int mi = 0; mi < 2; mi++)
            #pragma unroll
            for (int h = 0; h < 2; h++)
                rs[wm + mi * 16 + grp + h * 8] += rsum[mi][h];
    }
    __syncthreads();
    if (tid < 128) {
        int m = m0 + tid;
        if (m < HW)
            psum[((size_t)b * NTB + blockIdx.x) * HW + m] = rs[tid];
    }
}

// ---------------- 2b) attn GEMM: 128x128, split-K, ldmatrix, 3 stages --------
__global__ __launch_bounds__(256, 2)
void gemm_h(const __half* __restrict__ Aall, const __half* __restrict__ Ball,
            float* __restrict__ Call, int ldk, int nIter, int Mg, int Ng,
            size_t strideA, size_t strideB, size_t strideC, int nSplit) {
    extern __shared__ __align__(16) char smh[];
    uint32_t sbase = smem_u32(smh);
    int tid = threadIdx.x;
    int wid = tid >> 5, lane = tid & 31;
    int grp = lane >> 2, tig = lane & 3;
    int wm = (wid & 3) * 32;
    int wn = (wid >> 2) * 64;
    int z   = blockIdx.z;
    int b   = z / nSplit;
    int ksp = z - b * nSplit;
    int m0 = blockIdx.y * 128;
    int n0 = blockIdx.x * 128;
    const __half* A = Aall + (size_t)b * strideA;
    const __half* B = Ball + (size_t)b * strideB;
    float* Cb = Call + (size_t)z * strideC;

    int per = (nIter + nSplit - 1) / nSplit;
    int i0  = ksp * per;
    int i1  = min(nIter, i0 + per);
    int nit = i1 - i0;

    float acc[2][8][4];
    #pragma unroll
    for (int mi = 0; mi < 2; mi++)
        #pragma unroll
        for (int ni = 0; ni < 8; ni++)
            #pragma unroll
            for (int j = 0; j < 4; j++) acc[mi][ni][j] = 0.f;

    uint32_t hiA = lane >> 4;
    uint32_t aOff[2], aR7[2];
    #pragma unroll
    for (int mi = 0; mi < 2; mi++) {
        int r = wm + mi * 16 + (lane & 15);
        aOff[mi] = r * 128;
        aR7[mi]  = r & 7;
    }
    uint32_t quad = lane >> 3;
    uint32_t hiB = quad & 1;
    uint32_t bOff[4], bR7[4];
    #pragma unroll
    for (int nt = 0; nt < 4; nt++) {
        int r = wn + nt * 16 + ((quad >> 1) << 3) + (lane & 7);
        bOff[nt] = r * 128;
        bR7[nt]  = r & 7;
    }

    auto load_tile = [&](int iter, int s) {
        int k0 = iter * 64;
        uint32_t stA = sbase + s * STG_B;
        #pragma unroll
        for (int j = 0; j < 4; j++) {
            int f = tid + j * 256;
            int row = f >> 3, q = f & 7;
            uint32_t nb = (m0 + row < Mg) ? 16u : 0u;
            const __half* gp = A + (size_t)(nb ? m0 + row : 0) * ldk + k0 + q * 8;
            uint32_t sa = stA + row * 128 + ((q ^ (row & 7)) << 4);
            asm volatile("cp.async.cg.shared.global [%0], [%1], 16, %2;"
                         :: "r"(sa), "l"(gp), "r"(nb) : "memory");
        }
        #pragma unroll
        for (int j = 0; j < 4; j++) {
            int f = tid + j * 256;
            int row = f >> 3, q = f & 7;
            uint32_t nb = (n0 + row < Ng) ? 16u : 0u;
            const __half* gp = B + (size_t)(nb ? n0 + row : 0) * ldk + k0 + q * 8;
            uint32_t sa = stA + 16384 + row * 128 + ((q ^ (row & 7)) << 4);
            asm volatile("cp.async.cg.shared.global [%0], [%1], 16, %2;"
                         :: "r"(sa), "l"(gp), "r"(nb) : "memory");
        }
        asm volatile("cp.async.commit_group;" ::: "memory");
    };

    load_tile(i0, 0);
    if (nit > 1) load_tile(i0 + 1, 1);

    for (int j = 0; j < nit; j++) {
        int s = j % 3;
        if (j + 1 < nit) { asm volatile("cp.async.wait_group 1;" ::: "memory"); }
        else            { asm volatile("cp.async.wait_group 0;" ::: "memory"); }
        __syncthreads();
        if (j + 2 < nit) load_tile(i0 + j + 2, (j + 2) % 3);

        uint32_t stA = sbase + s * STG_B;
        uint32_t stB = stA + 16384;
        #pragma unroll
        for (int ks = 0; ks < 4; ks++) {
            uint32_t kk2 = ks * 2;
            uint32_t af[2][4];
            #pragma unroll
            for (int mi = 0; mi < 2; mi++) {
                uint32_t q = (kk2 + hiA) ^ aR7[mi];
                ldsm4(af[mi][0], af[mi][1], af[mi][2], af[mi][3],
                      stA + aOff[mi] + (q << 4));
            }
            uint32_t bf[8][2];
            #pragma unroll
            for (int nt = 0; nt < 4; nt++) {
                uint32_t q = (kk2 + hiB) ^ bR7[nt];
                uint32_t r0, r1, r2, r3;
                ldsm4(r0, r1, r2, r3, stB + bOff[nt] + (q << 4));
                bf[2 * nt][0] = r0; bf[2 * nt][1] = r1;
                bf[2 * nt + 1][0] = r2; bf[2 * nt + 1][1] = r3;
            }
            #pragma unroll
            for (int mi = 0; mi < 2; mi++)
                #pragma unroll
                for (int ni = 0; ni < 8; ni++)
                    mma_f16(acc[mi][ni], af[mi], bf[ni]);
        }
    }

    #pragma unroll
    for (int mi = 0; mi < 2; mi++) {
        int mrow = m0 + wm + mi * 16 + grp;
        #pragma unroll
        for (int ni = 0; ni < 8; ni++) {
            int n = n0 + wn + ni * 8 + 2 * tig;
            if (n < Ng) {
                if (mrow < Mg)
                    *(float2*)&Cb[(size_t)mrow * HW + n] =
                        make_float2(acc[mi][ni][0], acc[mi][ni][1]);
                if (mrow + 8 < Mg)
                    *(float2*)&Cb[(size_t)(mrow + 8) * HW + n] =
                        make_float2(acc[mi][ni][2], acc[mi][ni][3]);
            }
        }
    }
}

// ---------------- 3) f_s -> half, K-padded, vectorized ------------------------
__global__ void vprep_kernel(const float* __restrict__ V) {
    int idx = blockIdx.x * blockDim.x + threadIdx.x;
    if (idx >= NB * CQ * KP / 2) return;
    int s2 = idx % (KP / 2);
    int bc = idx / (KP / 2);
    int s  = 2 * s2;
    __half2 h;
    if (s + 1 < HW) {
        float2 v = *(const float2*)&V[(size_t)bc * HW + s];
        h = __floats2half2_rn(v.x, v.y);
    } else {
        h = __floats2half2_rn(0.f, 0.f);
    }
    *(__half2*)&g_Vh[(size_t)bc * KP + s] = h;
}

// ---------------- 4) combine: split-K + denom reduce + outputs ----------------
__global__ void combine_kernel(const float* __restrict__ f_q,
                               float* __restrict__ out_fq,
                               float* __restrict__ out_att, int writeAtt) {
    int tid = threadIdx.x;
    int cg  = tid >> 6;
    int pl  = tid & 63;
    int gpix = blockIdx.x * 64 + pl;
    bool pv = (gpix < NB * HW);
    int b = pv ? gpix / HW : 0;
    int p = pv ? gpix % HW : 0;

    const float* qb = f_q + (size_t)b * CQ * HW + p;
    const float* a0 = g_attP + ((size_t)2 * b) * CQ * HW + p;
    const float* a1 = g_attP + ((size_t)2 * b + 1) * CQ * HW + p;

    float sq = 0.f, sa = 0.f;
    if (pv) {
        #pragma unroll 8
        for (int c = cg * 64; c < cg * 64 + 64; c++) {
            float x = qb[(size_t)c * HW]; sq += x * x;
            float y = a0[(size_t)c * HW] + a1[(size_t)c * HW]; sa += y * y;
        }
    }
    float ds = 0.f;
    if (pv) {
        #pragma unroll
        for (int t = cg; t < NTB; t += 4)
            ds += g_psum[((size_t)b * NTB + t) * HW + p];
    }
    __shared__ float sQ[4][64], sA[4][64], sD[4][64];
    sQ[cg][pl] = sq;
    sA[cg][pl] = sa;
    sD[cg][pl] = ds;
    __syncthreads();
    float tq = sQ[0][pl] + sQ[1][pl] + sQ[2][pl] + sQ[3][pl];
    float ta = sA[0][pl] + sA[1][pl] + sA[2][pl] + sA[3][pl];
    float td = sD[0][pl] + sD[1][pl] + sD[2][pl] + sD[3][pl];
    float iq = 1.f / fmaxf(sqrtf(tq), EPS);
    float ia = ATT_WT / fmaxf(sqrtf(ta), EPS);
    float rsden = 1.f / td;

    if (pv) {
        float* ob = out_fq + (size_t)b * CQ * HW + p;
        if (writeAtt) {
            float* oa = out_att + (size_t)b * CQ * HW + p;
            #pragma unroll 4
            for (int c = cg * 64; c < cg * 64 + 64; c++) {
                float y = a0[(size_t)c * HW] + a1[(size_t)c * HW];
                ob[(size_t)c * HW] = qb[(size_t)c * HW] * iq + y * ia;
                oa[(size_t)c * HW] = y * rsden;
            }
        } else {
            #pragma unroll 4
            for (int c = cg * 64; c < cg * 64 + 64; c++) {
                float y = a0[(size_t)c * HW] + a1[(size_t)c * HW];
                ob[(size_t)c * HW] = qb[(size_t)c * HW] * iq + y * ia;
            }
        }
    }
}

// ---------------- launch ------------------------------------------------------
extern "C" void kernel_launch(void* const* d_in, const int* in_sizes, int n_in,
                              void* d_out, int out_size) {
    const float *fq3 = 0, *fs3 = 0, *fq4 = 0, *fs4 = 0, *f_q = 0, *f_s = 0;
    for (int i = 0; i < n_in; i++) {
        const float* p = (const float*)d_in[i];
        int sz = in_sizes[i];
        if (sz == SZ3)      { if (!fq3) fq3 = p; else fs3 = p; }
        else if (sz == SZ4) { if (!fq4) fq4 = p; else fs4 = p; }
        else if (sz == SZQ) { if (!f_q) f_q = p; else f_s = p; }
    }
    float* out = (float*)d_out;

    // TRUE device addresses (host shadow symbols are ATS-dereferenceable on
    // GB300 -> silent zero-data bug if passed directly).
    void *pAh, *pBh, *pAttnH, *pVh, *pAttP, *pPsum;
    cudaGetSymbolAddress(&pAh, g_Ah);
    cudaGetSymbolAddress(&pBh, g_Bh);
    cudaGetSymbolAddress(&pAttnH, g_attnH);
    cudaGetSymbolAddress(&pVh, g_Vh);
    cudaGetSymbolAddress(&pAttP, g_attP);
    cudaGetSymbolAddress(&pPsum, g_psum);

    cudaFuncSetAttribute(corr_gemm, cudaFuncAttributeMaxDynamicSharedMemorySize, GEMM_SMEM);
    cudaFuncSetAttribute(gemm_h, cudaFuncAttributeMaxDynamicSharedMemorySize, GEMM_SMEM);

    norms4_kernel<<<dim3(114, 2, 8), 256>>>(fq4, fs4, fq3, fs3);

    transpose_kernel<<<dim3(113, 48, NB * 2), 256>>>(fq4, fs4, fq3, fs3);

    vprep_kernel<<<(NB * CQ * KP / 2 + 255) / 256, 256>>>(f_s);

    // corr GEMM with fused exp(10*logit) epilogue -> attnH (half) + psum
    corr_gemm<<<dim3(NTB, NTB, NB), 256, GEMM_SMEM>>>(
        (const __half*)pAh, (const __half*)pBh, (__half*)pAttnH, (float*)pPsum);

    // attn GEMM with split-K=2: partials into g_attP (reduced inside combine)
    gemm_h<<<dim3(29, 2, NB * 2), 256, GEMM_SMEM>>>(
        (const __half*)pVh, (const __half*)pAttnH, (float*)pAttP,
        KP, KP / 64, CQ, HW,
        (size_t)CQ * KP, (size_t)HW * KP, (size_t)CQ * HW, 2);

    int writeAtt = (out_size >= 2 * SZQ) ? 1 : 0;
    combine_kernel<<<113, 256>>>(f_q, out, out + SZQ, writeAtt);
}